// round 4
// baseline (speedup 1.0000x reference)
#include <cuda_runtime.h>

#define TEAMN 5
#define BSZ   16384
#define NROW  (BSZ * TEAMN)      // 81920 member rows
#define NPAIR 20
#define MROW  (BSZ * NPAIR)      // 327680 pair rows
#define SPAD  68                 // padded SMEM row stride (floats): 16B-aligned, conflict-free STS

// ---------------- scratch (static device globals; no runtime allocation) ----
__device__ float g_h1[(size_t)NROW * 512];   // silu(x@fm_w1^T+b1)
__device__ float g_h [(size_t)NROW * 256];   // h
__device__ float g_wh[(size_t)NROW * 256];   // h@att_w^T+att_b   (per-member, reused by 4 pairs)
__device__ float g_o2[(size_t)BSZ * NPAIR];  // order2 (pre-bias2)

__constant__ int c_i1[NPAIR] = {0,0,0,0, 1,1,1,1, 2,2,2,2, 3,3,3,3, 4,4,4,4};
__constant__ int c_i2[NPAIR] = {1,2,3,4, 0,2,3,4, 0,1,3,4, 0,1,2,4, 0,1,2,3};

__device__ __forceinline__ float siluf(float x) { return x / (1.0f + __expf(-x)); }

// ---------------------------------------------------------------------------
// Generic tiled SGEMM:  C[M,N] = act(A[M,K] @ W[N,K]^T + bias)
// BM=BN=64, BK=32, 256 threads, 4x4 microtile.
// MODE 0: A gathered through ids (emb rows), epilogue silu.
// MODE 1: plain A, epilogue bias only.
// ---------------------------------------------------------------------------
template <int MODE, int K>
__global__ __launch_bounds__(256)
void gemm_k(const float* __restrict__ A, const float* __restrict__ W,
            const float* __restrict__ bias, float* __restrict__ C,
            const int* __restrict__ ids, int N)
{
    __shared__ __align__(16) float As[32][SPAD];
    __shared__ __align__(16) float Ws[32][SPAD];
    __shared__ int idS[64];

    const int t  = threadIdx.x;
    const int tx = t & 15;
    const int ty = t >> 4;
    const int m0 = blockIdx.y * 64;
    const int n0 = blockIdx.x * 64;

    if (MODE == 0) {
        if (t < 64) idS[t] = ids[m0 + t];
        __syncthreads();
    }

    float acc[4][4];
#pragma unroll
    for (int i = 0; i < 4; i++)
#pragma unroll
        for (int j = 0; j < 4; j++) acc[i][j] = 0.f;

    for (int k0 = 0; k0 < K; k0 += 32) {
#pragma unroll
        for (int u = 0; u < 2; u++) {
            int f   = t + u * 256;
            int row = f >> 3;
            int kc  = (f & 7) << 2;
            const float* asrc = (MODE == 0)
                ? (A + (size_t)idS[row] * K + k0 + kc)
                : (A + (size_t)(m0 + row) * K + k0 + kc);
            float4 v = *(const float4*)asrc;
            As[kc + 0][row] = v.x; As[kc + 1][row] = v.y;
            As[kc + 2][row] = v.z; As[kc + 3][row] = v.w;
            float4 w = *(const float4*)(W + (size_t)(n0 + row) * K + k0 + kc);
            Ws[kc + 0][row] = w.x; Ws[kc + 1][row] = w.y;
            Ws[kc + 2][row] = w.z; Ws[kc + 3][row] = w.w;
        }
        __syncthreads();
#pragma unroll
        for (int kk = 0; kk < 32; kk++) {
            float a[4], w[4];
            *(float4*)a = *(const float4*)&As[kk][ty * 4];
            *(float4*)w = *(const float4*)&Ws[kk][tx * 4];
#pragma unroll
            for (int i = 0; i < 4; i++)
#pragma unroll
                for (int j = 0; j < 4; j++)
                    acc[i][j] += a[i] * w[j];
        }
        __syncthreads();
    }

    const int n = n0 + tx * 4;
    float4 bz = *(const float4*)&bias[n];
#pragma unroll
    for (int i = 0; i < 4; i++) {
        float4 c;
        c.x = acc[i][0] + bz.x; c.y = acc[i][1] + bz.y;
        c.z = acc[i][2] + bz.z; c.w = acc[i][3] + bz.w;
        if (MODE == 0) {
            c.x = siluf(c.x); c.y = siluf(c.y); c.z = siluf(c.z); c.w = siluf(c.w);
        }
        *(float4*)&C[(size_t)(m0 + ty * 4 + i) * N + n] = c;
    }
}

// ---------------------------------------------------------------------------
// Pair-MLP kernel (dominant, 86 GF):
// rows = (batch, pair); A row = h[b,i1] ⊙ h[b,i2] built during the SMEM load;
// loops over all N=512 inside the block, epilogue folds silu(.)·mlp_w2 into a
// per-row scalar (order2) — single writer, no atomics, deterministic.
// ---------------------------------------------------------------------------
__global__ __launch_bounds__(256)
void pairs_k(const float* __restrict__ H, const float* __restrict__ W,
             const float* __restrict__ b1, const float* __restrict__ w2,
             float* __restrict__ O2)
{
    __shared__ __align__(16) float As[32][SPAD];
    __shared__ __align__(16) float Ws[32][SPAD];
    __shared__ int off1[64], off2[64];

    const int t  = threadIdx.x;
    const int tx = t & 15;
    const int ty = t >> 4;
    const int m0 = blockIdx.x * 64;

    if (t < 64) {
        int r = m0 + t;
        int b = r / NPAIR;
        int p = r - b * NPAIR;
        off1[t] = (b * TEAMN + c_i1[p]) * 256;
        off2[t] = (b * TEAMN + c_i2[p]) * 256;
    }
    __syncthreads();

    float rowsum[4] = {0.f, 0.f, 0.f, 0.f};

    for (int n0 = 0; n0 < 512; n0 += 64) {
        float acc[4][4];
#pragma unroll
        for (int i = 0; i < 4; i++)
#pragma unroll
            for (int j = 0; j < 4; j++) acc[i][j] = 0.f;

        for (int k0 = 0; k0 < 256; k0 += 32) {
#pragma unroll
            for (int u = 0; u < 2; u++) {
                int f   = t + u * 256;
                int row = f >> 3;
                int kc  = (f & 7) << 2;
                float4 v1 = *(const float4*)(H + off1[row] + k0 + kc);
                float4 v2 = *(const float4*)(H + off2[row] + k0 + kc);
                As[kc + 0][row] = v1.x * v2.x; As[kc + 1][row] = v1.y * v2.y;
                As[kc + 2][row] = v1.z * v2.z; As[kc + 3][row] = v1.w * v2.w;
                float4 w = *(const float4*)(W + (size_t)(n0 + row) * 256 + k0 + kc);
                Ws[kc + 0][row] = w.x; Ws[kc + 1][row] = w.y;
                Ws[kc + 2][row] = w.z; Ws[kc + 3][row] = w.w;
            }
            __syncthreads();
#pragma unroll
            for (int kk = 0; kk < 32; kk++) {
                float a[4], w[4];
                *(float4*)a = *(const float4*)&As[kk][ty * 4];
                *(float4*)w = *(const float4*)&Ws[kk][tx * 4];
#pragma unroll
                for (int i = 0; i < 4; i++)
#pragma unroll
                    for (int j = 0; j < 4; j++)
                        acc[i][j] += a[i] * w[j];
            }
            __syncthreads();
        }

        const int n = n0 + tx * 4;
        float4 bb = *(const float4*)&b1[n];
        float4 ww = *(const float4*)&w2[n];
#pragma unroll
        for (int i = 0; i < 4; i++) {
            rowsum[i] += siluf(acc[i][0] + bb.x) * ww.x
                       + siluf(acc[i][1] + bb.y) * ww.y
                       + siluf(acc[i][2] + bb.z) * ww.z
                       + siluf(acc[i][3] + bb.w) * ww.w;
        }
    }

#pragma unroll
    for (int off = 8; off > 0; off >>= 1)
#pragma unroll
        for (int i = 0; i < 4; i++)
            rowsum[i] += __shfl_down_sync(0xffffffffu, rowsum[i], off, 16);

    if (tx == 0) {
#pragma unroll
        for (int i = 0; i < 4; i++)
            O2[m0 + ty * 4 + i] = rowsum[i];
    }
}

// ---------------------------------------------------------------------------
// Final kernel: score[p] = <wh[b,i1], h[b,i2]>, softmax over groups of 4,
// out[b] = sum_p softmax_p * (order2_p + mlp_b2). One warp per batch.
// ---------------------------------------------------------------------------
__global__ __launch_bounds__(128)
void final_k(const float* __restrict__ H, const float* __restrict__ WH,
             const float* __restrict__ O2, const float* __restrict__ mlp_b2,
             float* __restrict__ out)
{
    __shared__ float scoreS[4][NPAIR];
    const int wi   = threadIdx.x >> 5;
    const int lane = threadIdx.x & 31;
    const int b    = blockIdx.x * 4 + wi;
    const float* hb  = H  + (size_t)b * TEAMN * 256;
    const float* whb = WH + (size_t)b * TEAMN * 256;

    for (int p = 0; p < NPAIR; p++) {
        const float* wa = whb + c_i1[p] * 256;
        const float* hv = hb  + c_i2[p] * 256;
        float4 x1 = *(const float4*)(wa + lane * 8);
        float4 x2 = *(const float4*)(wa + lane * 8 + 4);
        float4 y1 = *(const float4*)(hv + lane * 8);
        float4 y2 = *(const float4*)(hv + lane * 8 + 4);
        float s = x1.x * y1.x + x1.y * y1.y + x1.z * y1.z + x1.w * y1.w
                + x2.x * y2.x + x2.y * y2.y + x2.z * y2.z + x2.w * y2.w;
#pragma unroll
        for (int off = 16; off > 0; off >>= 1)
            s += __shfl_down_sync(0xffffffffu, s, off);
        if (lane == 0) scoreS[wi][p] = s;
    }
    __syncwarp();

    float partial = 0.f;
    if (lane < TEAMN) {
        float sc[4];
#pragma unroll
        for (int j = 0; j < 4; j++) sc[j] = scoreS[wi][lane * 4 + j];
        float mx = fmaxf(fmaxf(sc[0], sc[1]), fmaxf(sc[2], sc[3]));
        float e[4], se = 0.f;
#pragma unroll
        for (int j = 0; j < 4; j++) { e[j] = __expf(sc[j] - mx); se += e[j]; }
        float bias2 = mlp_b2[0];
        float acc = 0.f;
#pragma unroll
        for (int j = 0; j < 4; j++)
            acc += e[j] * (O2[b * NPAIR + lane * 4 + j] + bias2);
        partial = acc / se;
    }
#pragma unroll
    for (int off = 16; off > 0; off >>= 1)
        partial += __shfl_down_sync(0xffffffffu, partial, off);
    if (lane == 0) out[b] = partial;
}

// ---------------------------------------------------------------------------
extern "C" void kernel_launch(void* const* d_in, const int* in_sizes, int n_in,
                              void* d_out, int out_size)
{
    const int*   team_ids = (const int*)  d_in[0];
    const float* emb      = (const float*)d_in[1];
    const float* fm_w1    = (const float*)d_in[2];
    const float* fm_b1    = (const float*)d_in[3];
    const float* fm_w2    = (const float*)d_in[4];
    const float* fm_b2    = (const float*)d_in[5];
    const float* att_w    = (const float*)d_in[6];
    const float* att_b    = (const float*)d_in[7];
    const float* mlp_w1   = (const float*)d_in[8];
    const float* mlp_b1   = (const float*)d_in[9];
    const float* mlp_w2   = (const float*)d_in[10];
    const float* mlp_b2   = (const float*)d_in[11];
    float* out = (float*)d_out;

    void *p_h1, *p_h, *p_wh, *p_o2;
    cudaGetSymbolAddress(&p_h1, g_h1);
    cudaGetSymbolAddress(&p_h,  g_h);
    cudaGetSymbolAddress(&p_wh, g_wh);
    cudaGetSymbolAddress(&p_o2, g_o2);

    // fm1: gather + silu(x @ fm_w1^T + b1)   -> g_h1 [81920,512]
    gemm_k<0, 256><<<dim3(512 / 64, NROW / 64), 256>>>(
        emb, fm_w1, fm_b1, (float*)p_h1, team_ids, 512);
    // fm2: g_h1 @ fm_w2^T + b2               -> g_h  [81920,256]
    gemm_k<1, 512><<<dim3(256 / 64, NROW / 64), 256>>>(
        (const float*)p_h1, fm_w2, fm_b2, (float*)p_h, nullptr, 256);
    // att (hoisted per member): g_h @ att_w^T + att_b -> g_wh [81920,256]
    gemm_k<1, 256><<<dim3(256 / 64, NROW / 64), 256>>>(
        (const float*)p_h, att_w, att_b, (float*)p_wh, nullptr, 256);
    // pair MLP + order2 reduction            -> g_o2 [16384,20]
    pairs_k<<<MROW / 64, 256>>>(
        (const float*)p_h, mlp_w1, mlp_b1, mlp_w2, (float*)p_o2);
    // scores + softmax + weighted sum        -> out [16384]
    final_k<<<BSZ / 4, 128>>>(
        (const float*)p_h, (const float*)p_wh, (const float*)p_o2, mlp_b2, out);
}

// round 5
// speedup vs baseline: 2.3040x; 2.3040x over previous
#include <cuda_runtime.h>
#include <cuda_bf16.h>
#include <cstdint>

#define TEAMN   5
#define BSZ     16384
#define NROW    (BSZ * TEAMN)     // 81920 member rows
#define NPAIR   20
#define MROW    (BSZ * NPAIR)     // 327680 pair rows
#define NPLAYER 131072
#define PD      256

// ---------------- scratch (static device globals; no runtime allocation) ----
__device__ __nv_bfloat16 g_ehi [(size_t)NPLAYER * PD];
__device__ __nv_bfloat16 g_elo [(size_t)NPLAYER * PD];
__device__ __nv_bfloat16 g_h1hi[(size_t)NROW * 512];
__device__ __nv_bfloat16 g_h1lo[(size_t)NROW * 512];
__device__ __nv_bfloat16 g_hhi [(size_t)NROW * 256];
__device__ __nv_bfloat16 g_hlo [(size_t)NROW * 256];
__device__ float         g_wh  [(size_t)NROW * 256];
__device__ float         g_o2  [(size_t)BSZ * NPAIR];
__device__ __nv_bfloat16 g_w1hi[512 * 256], g_w1lo[512 * 256];
__device__ __nv_bfloat16 g_w2hi[256 * 512], g_w2lo[256 * 512];
__device__ __nv_bfloat16 g_awhi[256 * 256], g_awlo[256 * 256];
__device__ __nv_bfloat16 g_m1hi[512 * 256], g_m1lo[512 * 256];

__constant__ int c_i1[NPAIR] = {0,0,0,0, 1,1,1,1, 2,2,2,2, 3,3,3,3, 4,4,4,4};
__constant__ int c_i2[NPAIR] = {1,2,3,4, 0,2,3,4, 0,1,3,4, 0,1,2,4, 0,1,2,3};

__device__ __forceinline__ float siluf(float x) { return x / (1.0f + __expf(-x)); }

__device__ __forceinline__ unsigned smem_u32(const void* p) {
    return (unsigned)__cvta_generic_to_shared(p);
}
__device__ __forceinline__ void ldsm_x4(uint32_t* r, unsigned addr) {
    asm volatile("ldmatrix.sync.aligned.m8n8.x4.shared.b16 {%0,%1,%2,%3}, [%4];"
                 : "=r"(r[0]), "=r"(r[1]), "=r"(r[2]), "=r"(r[3]) : "r"(addr));
}
__device__ __forceinline__ void ldsm_x2(uint32_t* r, unsigned addr) {
    asm volatile("ldmatrix.sync.aligned.m8n8.x2.shared.b16 {%0,%1}, [%2];"
                 : "=r"(r[0]), "=r"(r[1]) : "r"(addr));
}
__device__ __forceinline__ void mma16816(float* c, const uint32_t* a, const uint32_t* b) {
    asm volatile(
        "mma.sync.aligned.m16n8k16.row.col.f32.bf16.bf16.f32 "
        "{%0,%1,%2,%3}, {%4,%5,%6,%7}, {%8,%9}, {%0,%1,%2,%3};"
        : "+f"(c[0]), "+f"(c[1]), "+f"(c[2]), "+f"(c[3])
        : "r"(a[0]), "r"(a[1]), "r"(a[2]), "r"(a[3]), "r"(b[0]), "r"(b[1]));
}
__device__ __forceinline__ void store_split2(__nv_bfloat16* hi, __nv_bfloat16* lo,
                                             size_t off, float y0, float y1) {
    __nv_bfloat16 h0 = __float2bfloat16(y0), h1 = __float2bfloat16(y1);
    *(__nv_bfloat162*)(hi + off) = __halves2bfloat162(h0, h1);
    *(__nv_bfloat162*)(lo + off) = __halves2bfloat162(
        __float2bfloat16(y0 - __bfloat162float(h0)),
        __float2bfloat16(y1 - __bfloat162float(h1)));
}

// ---------------------------------------------------------------------------
// Split fp32 -> (hi, lo) bf16 pair
// ---------------------------------------------------------------------------
__global__ void split_k(const float* __restrict__ s, __nv_bfloat16* __restrict__ hi,
                        __nv_bfloat16* __restrict__ lo, int n) {
    int i = blockIdx.x * 256 + threadIdx.x;
    if (i >= n) return;
    float v = s[i];
    __nv_bfloat16 h = __float2bfloat16(v);
    hi[i] = h;
    lo[i] = __float2bfloat16(v - __bfloat162float(h));
}

// ---------------------------------------------------------------------------
// Split-bf16 tensor-core GEMM:  C[M,N] = ep(A[M,K] @ W[N,K]^T + bias)
// A,W given as (hi,lo) pairs; 3 K-segments: (hi,hi),(lo,hi),(hi,lo).
// 128x128x32 block, 8 warps (2x4), m16n8k16 mma, 2-buffer pipeline.
// EP: 0 = silu + split-store   1 = split-store   2 = fp32 store
// ---------------------------------------------------------------------------
template <int K, int EP, bool GATHER>
__global__ __launch_bounds__(256)
void mma_gemm_k(const __nv_bfloat16* __restrict__ Ahi, const __nv_bfloat16* __restrict__ Alo,
                const __nv_bfloat16* __restrict__ Whi, const __nv_bfloat16* __restrict__ Wlo,
                const float* __restrict__ bias,
                __nv_bfloat16* __restrict__ Chi, __nv_bfloat16* __restrict__ Clo,
                float* __restrict__ Cf, const int* __restrict__ ids, int N)
{
    constexpr int KIT = K / 32;
    constexpr int NIT = 3 * KIT;
    __shared__ __align__(16) __nv_bfloat16 As[2][128][40];
    __shared__ __align__(16) __nv_bfloat16 Ws[2][128][40];
    __shared__ int idS[128];

    const int t = threadIdx.x;
    const int lane = t & 31, warp = t >> 5;
    const int wm = warp >> 2, wn = warp & 3;
    const int m0 = blockIdx.y * 128, n0 = blockIdx.x * 128;

    if constexpr (GATHER) {
        if (t < 128) idS[t] = ids[m0 + t];
        __syncthreads();
    }

    float acc[4][4][4];
#pragma unroll
    for (int a = 0; a < 4; a++)
#pragma unroll
        for (int b = 0; b < 4; b++)
#pragma unroll
            for (int c = 0; c < 4; c++) acc[a][b][c] = 0.f;

    const int a_mrow = ((lane >> 3) & 1) * 8 + (lane & 7);
    const int a_kc   = (lane >> 4) * 8;
    const int bl     = lane & 15;
    const int b_nrow = bl & 7;
    const int b_kc   = ((bl >> 3) & 1) * 8;

    uint4 ra[2], rw[2];
    // prologue fetch it=0
    {
        const __nv_bfloat16* pa = Ahi;
        const __nv_bfloat16* pw = Whi;
#pragma unroll
        for (int u = 0; u < 2; u++) {
            int idx = t + u * 256, row = idx >> 2, ch = (idx & 3) << 3;
            size_t arow = GATHER ? (size_t)idS[row] : (size_t)(m0 + row);
            ra[u] = *(const uint4*)(pa + arow * K + ch);
            rw[u] = *(const uint4*)(pw + (size_t)(n0 + row) * K + ch);
        }
    }

    int buf = 0;
    for (int it = 0; it < NIT; it++) {
#pragma unroll
        for (int u = 0; u < 2; u++) {
            int idx = t + u * 256, row = idx >> 2, ch = (idx & 3) << 3;
            *(uint4*)&As[buf][row][ch] = ra[u];
            *(uint4*)&Ws[buf][row][ch] = rw[u];
        }
        __syncthreads();
        if (it + 1 < NIT) {
            int seg = (it + 1) / KIT, kk = ((it + 1) % KIT) * 32;
            const __nv_bfloat16* pa = (seg == 1) ? Alo : Ahi;
            const __nv_bfloat16* pw = (seg == 2) ? Wlo : Whi;
#pragma unroll
            for (int u = 0; u < 2; u++) {
                int idx = t + u * 256, row = idx >> 2, ch = (idx & 3) << 3;
                size_t arow = GATHER ? (size_t)idS[row] : (size_t)(m0 + row);
                ra[u] = *(const uint4*)(pa + arow * K + kk + ch);
                rw[u] = *(const uint4*)(pw + (size_t)(n0 + row) * K + kk + ch);
            }
        }
        unsigned aB = smem_u32(&As[buf][0][0]);
        unsigned wB = smem_u32(&Ws[buf][0][0]);
#pragma unroll
        for (int ks = 0; ks < 2; ks++) {
            uint32_t bfrg[4][2];
#pragma unroll
            for (int nt = 0; nt < 4; nt++)
                ldsm_x2(bfrg[nt], wB + 2u * ((wn * 32 + nt * 8 + b_nrow) * 40 + ks * 16 + b_kc));
#pragma unroll
            for (int mt = 0; mt < 4; mt++) {
                uint32_t af[4];
                ldsm_x4(af, aB + 2u * ((wm * 64 + mt * 16 + a_mrow) * 40 + ks * 16 + a_kc));
#pragma unroll
                for (int nt = 0; nt < 4; nt++) mma16816(acc[mt][nt], af, bfrg[nt]);
            }
        }
        buf ^= 1;
    }

    // epilogue
#pragma unroll
    for (int mt = 0; mt < 4; mt++)
#pragma unroll
        for (int nt = 0; nt < 4; nt++) {
            int row = m0 + wm * 64 + mt * 16 + (lane >> 2);
            int col = n0 + wn * 32 + nt * 8 + ((lane & 3) << 1);
            float2 bz = *(const float2*)(bias + col);
            float* c = acc[mt][nt];
            float y0 = c[0] + bz.x, y1 = c[1] + bz.y;
            float y2 = c[2] + bz.x, y3 = c[3] + bz.y;
            if (EP == 0) { y0 = siluf(y0); y1 = siluf(y1); y2 = siluf(y2); y3 = siluf(y3); }
            if (EP <= 1) {
                store_split2(Chi, Clo, (size_t)row * N + col, y0, y1);
                store_split2(Chi, Clo, (size_t)(row + 8) * N + col, y2, y3);
            } else {
                *(float2*)(Cf + (size_t)row * N + col)       = make_float2(y0, y1);
                *(float2*)(Cf + (size_t)(row + 8) * N + col) = make_float2(y2, y3);
            }
        }
}

// ---------------------------------------------------------------------------
// Pair-MLP kernel: A row = h[b,i1] ⊙ h[b,i2] built ONCE per block (hi/lo split)
// into smem-resident tiles; W streamed; 3-way split mma; epilogue folds
// silu(+b1)·w2 into per-row sums -> O2.  Dynamic smem: 179200 B.
// ---------------------------------------------------------------------------
#define PAIRS_SMEM (2 * 128 * 264 * 2 + 2 * 2 * 128 * 40 * 2 + 256 * 4 + 512 * 4)

__global__ __launch_bounds__(256)
void pairs_mma_k(const __nv_bfloat16* __restrict__ Hhi, const __nv_bfloat16* __restrict__ Hlo,
                 const __nv_bfloat16* __restrict__ W1hi, const __nv_bfloat16* __restrict__ W1lo,
                 const float* __restrict__ b1, const float* __restrict__ w2,
                 float* __restrict__ O2)
{
    extern __shared__ __align__(16) char smraw[];
    __nv_bfloat16* Aphi = (__nv_bfloat16*)smraw;            // [128][264]
    __nv_bfloat16* Aplo = Aphi + 128 * 264;                 // [128][264]
    __nv_bfloat16* Wt   = Aplo + 128 * 264;                 // [2 buf][2 hl][128][40]
    int*   off1s = (int*)(Wt + 2 * 2 * 128 * 40);
    int*   off2s = off1s + 128;
    float* redS  = (float*)(off2s + 128);                   // [4][128]

    const int t = threadIdx.x, lane = t & 31, warp = t >> 5;
    const int wm = warp >> 2, wn = warp & 3;
    const int m0 = blockIdx.x * 128;

    if (t < 128) {
        int r = m0 + t, b = r / NPAIR, p = r - b * NPAIR;
        off1s[t] = (b * TEAMN + c_i1[p]) * 256;
        off2s[t] = (b * TEAMN + c_i2[p]) * 256;
    }
    __syncthreads();

    // ---- phase 1: build product tiles (hi/lo) ----
    {
        int cidx = t;
#pragma unroll 4
        for (int i = 0; i < 16; i++, cidx += 256) {
            int row = cidx >> 5;
            int ch  = (cidx & 31) << 3;
            int o1 = off1s[row] + ch, o2 = off2s[row] + ch;
            uint4 u1h = *(const uint4*)(Hhi + o1);
            uint4 u1l = *(const uint4*)(Hlo + o1);
            uint4 u2h = *(const uint4*)(Hhi + o2);
            uint4 u2l = *(const uint4*)(Hlo + o2);
            const __nv_bfloat162* p1h = (const __nv_bfloat162*)&u1h;
            const __nv_bfloat162* p1l = (const __nv_bfloat162*)&u1l;
            const __nv_bfloat162* p2h = (const __nv_bfloat162*)&u2h;
            const __nv_bfloat162* p2l = (const __nv_bfloat162*)&u2l;
            __nv_bfloat162 oph[4], opl[4];
#pragma unroll
            for (int j = 0; j < 4; j++) {
                float2 a  = __bfloat1622float2(p1h[j]);
                float2 al = __bfloat1622float2(p1l[j]);
                float2 b_ = __bfloat1622float2(p2h[j]);
                float2 bl_ = __bfloat1622float2(p2l[j]);
                float f0 = (a.x + al.x) * (b_.x + bl_.x);
                float f1 = (a.y + al.y) * (b_.y + bl_.y);
                __nv_bfloat16 h0 = __float2bfloat16(f0), h1 = __float2bfloat16(f1);
                oph[j] = __halves2bfloat162(h0, h1);
                opl[j] = __halves2bfloat162(
                    __float2bfloat16(f0 - __bfloat162float(h0)),
                    __float2bfloat16(f1 - __bfloat162float(h1)));
            }
            *(uint4*)(Aphi + row * 264 + ch) = *(uint4*)oph;
            *(uint4*)(Aplo + row * 264 + ch) = *(uint4*)opl;
        }
    }

    float rowsum[4][2];
#pragma unroll
    for (int a = 0; a < 4; a++) { rowsum[a][0] = 0.f; rowsum[a][1] = 0.f; }

    const int a_mrow = ((lane >> 3) & 1) * 8 + (lane & 7);
    const int a_kc   = (lane >> 4) * 8;
    const int bl     = lane & 15;
    const int b_nrow = bl & 7;
    const int b_kc   = ((bl >> 3) & 1) * 8;
    const unsigned aPhiB = smem_u32(Aphi);
    const unsigned aPloB = smem_u32(Aplo);
    const unsigned wB    = smem_u32(Wt);

    uint4 rwh[2], rwl[2];
#pragma unroll
    for (int u = 0; u < 2; u++) {    // prefetch n0=0, k0=0
        int idx = t + u * 256, row = idx >> 2, ch = (idx & 3) << 3;
        size_t go = (size_t)row * 256 + ch;
        rwh[u] = *(const uint4*)(W1hi + go);
        rwl[u] = *(const uint4*)(W1lo + go);
    }

    int buf = 0;
    for (int n0i = 0; n0i < 4; n0i++) {
        int n0 = n0i * 128;
        float acc[4][4][4];
#pragma unroll
        for (int a = 0; a < 4; a++)
#pragma unroll
            for (int b = 0; b < 4; b++)
#pragma unroll
                for (int c = 0; c < 4; c++) acc[a][b][c] = 0.f;

        for (int k0 = 0; k0 < 8; k0++) {
#pragma unroll
            for (int u = 0; u < 2; u++) {
                int idx = t + u * 256, row = idx >> 2, ch = (idx & 3) << 3;
                *(uint4*)(Wt + (buf * 2 + 0) * 5120 + row * 40 + ch) = rwh[u];
                *(uint4*)(Wt + (buf * 2 + 1) * 5120 + row * 40 + ch) = rwl[u];
            }
            __syncthreads();
            if (!(n0i == 3 && k0 == 7)) {
                int nk = k0 + 1, nn = n0i;
                if (nk == 8) { nk = 0; nn++; }
#pragma unroll
                for (int u = 0; u < 2; u++) {
                    int idx = t + u * 256, row = idx >> 2, ch = (idx & 3) << 3;
                    size_t go = (size_t)(nn * 128 + row) * 256 + nk * 32 + ch;
                    rwh[u] = *(const uint4*)(W1hi + go);
                    rwl[u] = *(const uint4*)(W1lo + go);
                }
            }
#pragma unroll
            for (int ks = 0; ks < 2; ks++) {
                int kpos = k0 * 32 + ks * 16;
                uint32_t bh[4][2], blo_[4][2];
#pragma unroll
                for (int nt = 0; nt < 4; nt++) {
                    unsigned wo = (wn * 32 + nt * 8 + b_nrow) * 40 + ks * 16 + b_kc;
                    ldsm_x2(bh[nt],   wB + 2u * ((buf * 2 + 0) * 5120 + wo));
                    ldsm_x2(blo_[nt], wB + 2u * ((buf * 2 + 1) * 5120 + wo));
                }
#pragma unroll
                for (int mt = 0; mt < 4; mt++) {
                    unsigned ao = (wm * 64 + mt * 16 + a_mrow) * 264 + kpos + a_kc;
                    uint32_t af[4];
                    ldsm_x4(af, aPhiB + 2u * ao);
#pragma unroll
                    for (int nt = 0; nt < 4; nt++) mma16816(acc[mt][nt], af, bh[nt]);
#pragma unroll
                    for (int nt = 0; nt < 4; nt++) mma16816(acc[mt][nt], af, blo_[nt]);
                    ldsm_x4(af, aPloB + 2u * ao);
#pragma unroll
                    for (int nt = 0; nt < 4; nt++) mma16816(acc[mt][nt], af, bh[nt]);
                }
            }
            buf ^= 1;
        }
        // fold this n-chunk into rowsums
#pragma unroll
        for (int mt = 0; mt < 4; mt++)
#pragma unroll
            for (int nt = 0; nt < 4; nt++) {
                int col = n0 + wn * 32 + nt * 8 + ((lane & 3) << 1);
                float2 bz = *(const float2*)(b1 + col);
                float2 wz = *(const float2*)(w2 + col);
                float* c = acc[mt][nt];
                rowsum[mt][0] += siluf(c[0] + bz.x) * wz.x + siluf(c[1] + bz.y) * wz.y;
                rowsum[mt][1] += siluf(c[2] + bz.x) * wz.x + siluf(c[3] + bz.y) * wz.y;
            }
    }

    // reduce over the 4 lanes sharing a row, then across the 4 n-warps
#pragma unroll
    for (int mt = 0; mt < 4; mt++)
#pragma unroll
        for (int p = 0; p < 2; p++) {
            float v = rowsum[mt][p];
            v += __shfl_xor_sync(0xffffffffu, v, 1);
            v += __shfl_xor_sync(0xffffffffu, v, 2);
            rowsum[mt][p] = v;
        }
    __syncthreads();
    if ((lane & 3) == 0) {
#pragma unroll
        for (int mt = 0; mt < 4; mt++)
#pragma unroll
            for (int p = 0; p < 2; p++) {
                int r = wm * 64 + mt * 16 + (lane >> 2) + p * 8;
                redS[wn * 128 + r] = rowsum[mt][p];
            }
    }
    __syncthreads();
    if (t < 128)
        O2[m0 + t] = redS[t] + redS[128 + t] + redS[256 + t] + redS[384 + t];
}

// ---------------------------------------------------------------------------
// Final: score[p] = <wh[b,i1], h[b,i2]>, softmax per group-of-4, weighted sum.
// ---------------------------------------------------------------------------
__global__ __launch_bounds__(128)
void final_k(const __nv_bfloat16* __restrict__ Hhi, const __nv_bfloat16* __restrict__ Hlo,
             const float* __restrict__ WH, const float* __restrict__ O2,
             const float* __restrict__ mlp_b2, float* __restrict__ out)
{
    __shared__ float scoreS[4][NPAIR];
    const int wi = threadIdx.x >> 5, lane = threadIdx.x & 31;
    const int b = blockIdx.x * 4 + wi;
    const __nv_bfloat16* hbh = Hhi + (size_t)b * TEAMN * 256;
    const __nv_bfloat16* hbl = Hlo + (size_t)b * TEAMN * 256;
    const float* whb = WH + (size_t)b * TEAMN * 256;

    for (int p = 0; p < NPAIR; p++) {
        const float* wa = whb + c_i1[p] * 256;
        int ho = c_i2[p] * 256 + lane * 8;
        uint4 uh = *(const uint4*)(hbh + ho);
        uint4 ul = *(const uint4*)(hbl + ho);
        const __nv_bfloat162* ph = (const __nv_bfloat162*)&uh;
        const __nv_bfloat162* pl = (const __nv_bfloat162*)&ul;
        float xv[8];
        *(float4*)&xv[0] = *(const float4*)(wa + lane * 8);
        *(float4*)&xv[4] = *(const float4*)(wa + lane * 8 + 4);
        float s = 0.f;
#pragma unroll
        for (int j = 0; j < 4; j++) {
            float2 hh = __bfloat1622float2(ph[j]);
            float2 hl = __bfloat1622float2(pl[j]);
            s += xv[2 * j] * (hh.x + hl.x) + xv[2 * j + 1] * (hh.y + hl.y);
        }
#pragma unroll
        for (int off = 16; off > 0; off >>= 1)
            s += __shfl_down_sync(0xffffffffu, s, off);
        if (lane == 0) scoreS[wi][p] = s;
    }
    __syncwarp();

    float partial = 0.f;
    if (lane < TEAMN) {
        float sc[4];
#pragma unroll
        for (int j = 0; j < 4; j++) sc[j] = scoreS[wi][lane * 4 + j];
        float mx = fmaxf(fmaxf(sc[0], sc[1]), fmaxf(sc[2], sc[3]));
        float e[4], se = 0.f;
#pragma unroll
        for (int j = 0; j < 4; j++) { e[j] = __expf(sc[j] - mx); se += e[j]; }
        float bias2 = mlp_b2[0];
        float acc = 0.f;
#pragma unroll
        for (int j = 0; j < 4; j++)
            acc += e[j] * (O2[b * NPAIR + lane * 4 + j] + bias2);
        partial = acc / se;
    }
#pragma unroll
    for (int off = 16; off > 0; off >>= 1)
        partial += __shfl_down_sync(0xffffffffu, partial, off);
    if (lane == 0) out[b] = partial;
}

// ---------------------------------------------------------------------------
extern "C" void kernel_launch(void* const* d_in, const int* in_sizes, int n_in,
                              void* d_out, int out_size)
{
    const int*   team_ids = (const int*)  d_in[0];
    const float* emb      = (const float*)d_in[1];
    const float* fm_w1    = (const float*)d_in[2];
    const float* fm_b1    = (const float*)d_in[3];
    const float* fm_w2    = (const float*)d_in[4];
    const float* fm_b2    = (const float*)d_in[5];
    const float* att_w    = (const float*)d_in[6];
    const float* att_b    = (const float*)d_in[7];
    const float* mlp_w1   = (const float*)d_in[8];
    const float* mlp_b1   = (const float*)d_in[9];
    const float* mlp_w2   = (const float*)d_in[10];
    const float* mlp_b2   = (const float*)d_in[11];
    float* out = (float*)d_out;

    void *p_ehi, *p_elo, *p_h1hi, *p_h1lo, *p_hhi, *p_hlo, *p_wh, *p_o2;
    void *p_w1hi, *p_w1lo, *p_w2hi, *p_w2lo, *p_awhi, *p_awlo, *p_m1hi, *p_m1lo;
    cudaGetSymbolAddress(&p_ehi,  g_ehi);  cudaGetSymbolAddress(&p_elo,  g_elo);
    cudaGetSymbolAddress(&p_h1hi, g_h1hi); cudaGetSymbolAddress(&p_h1lo, g_h1lo);
    cudaGetSymbolAddress(&p_hhi,  g_hhi);  cudaGetSymbolAddress(&p_hlo,  g_hlo);
    cudaGetSymbolAddress(&p_wh,   g_wh);   cudaGetSymbolAddress(&p_o2,   g_o2);
    cudaGetSymbolAddress(&p_w1hi, g_w1hi); cudaGetSymbolAddress(&p_w1lo, g_w1lo);
    cudaGetSymbolAddress(&p_w2hi, g_w2hi); cudaGetSymbolAddress(&p_w2lo, g_w2lo);
    cudaGetSymbolAddress(&p_awhi, g_awhi); cudaGetSymbolAddress(&p_awlo, g_awlo);
    cudaGetSymbolAddress(&p_m1hi, g_m1hi); cudaGetSymbolAddress(&p_m1lo, g_m1lo);

    // split fp32 -> hi/lo bf16
    {
        int n = NPLAYER * PD;
        split_k<<<(n + 255) / 256, 256>>>(emb, (__nv_bfloat16*)p_ehi, (__nv_bfloat16*)p_elo, n);
    }
    split_k<<<(512 * 256 + 255) / 256, 256>>>(fm_w1,  (__nv_bfloat16*)p_w1hi, (__nv_bfloat16*)p_w1lo, 512 * 256);
    split_k<<<(256 * 512 + 255) / 256, 256>>>(fm_w2,  (__nv_bfloat16*)p_w2hi, (__nv_bfloat16*)p_w2lo, 256 * 512);
    split_k<<<(256 * 256 + 255) / 256, 256>>>(att_w,  (__nv_bfloat16*)p_awhi, (__nv_bfloat16*)p_awlo, 256 * 256);
    split_k<<<(512 * 256 + 255) / 256, 256>>>(mlp_w1, (__nv_bfloat16*)p_m1hi, (__nv_bfloat16*)p_m1lo, 512 * 256);

    // fm1: gather + silu(x @ fm_w1^T + b1) -> h1 (hi/lo)
    mma_gemm_k<256, 0, true><<<dim3(4, NROW / 128), 256>>>(
        (const __nv_bfloat16*)p_ehi, (const __nv_bfloat16*)p_elo,
        (const __nv_bfloat16*)p_w1hi, (const __nv_bfloat16*)p_w1lo,
        fm_b1, (__nv_bfloat16*)p_h1hi, (__nv_bfloat16*)p_h1lo, nullptr, team_ids, 512);
    // fm2: h1 @ fm_w2^T + b2 -> h (hi/lo)
    mma_gemm_k<512, 1, false><<<dim3(2, NROW / 128), 256>>>(
        (const __nv_bfloat16*)p_h1hi, (const __nv_bfloat16*)p_h1lo,
        (const __nv_bfloat16*)p_w2hi, (const __nv_bfloat16*)p_w2lo,
        fm_b2, (__nv_bfloat16*)p_hhi, (__nv_bfloat16*)p_hlo, nullptr, nullptr, 256);
    // att (hoisted per member): h @ att_w^T + att_b -> wh (fp32)
    mma_gemm_k<256, 2, false><<<dim3(2, NROW / 128), 256>>>(
        (const __nv_bfloat16*)p_hhi, (const __nv_bfloat16*)p_hlo,
        (const __nv_bfloat16*)p_awhi, (const __nv_bfloat16*)p_awlo,
        att_b, nullptr, nullptr, (float*)p_wh, nullptr, 256);
    // pair MLP + order2 reduction -> o2
    cudaFuncSetAttribute(pairs_mma_k, cudaFuncAttributeMaxDynamicSharedMemorySize, PAIRS_SMEM);
    pairs_mma_k<<<MROW / 128, 256, PAIRS_SMEM>>>(
        (const __nv_bfloat16*)p_hhi, (const __nv_bfloat16*)p_hlo,
        (const __nv_bfloat16*)p_m1hi, (const __nv_bfloat16*)p_m1lo,
        mlp_b1, mlp_w2, (float*)p_o2);
    // scores + softmax + weighted sum
    final_k<<<BSZ / 4, 128>>>(
        (const __nv_bfloat16*)p_hhi, (const __nv_bfloat16*)p_hlo,
        (const float*)p_wh, (const float*)p_o2, mlp_b2, out);
}

// round 6
// speedup vs baseline: 3.0985x; 1.3448x over previous
#include <cuda_runtime.h>
#include <cuda_bf16.h>
#include <cstdint>

#define TEAMN   5
#define BSZ     16384
#define NROW    (BSZ * TEAMN)     // 81920 member rows
#define NPAIR   20
#define NPAIR_U 10                // unique unordered pairs (prod is symmetric)
#define MROW_U  (BSZ * NPAIR_U)   // 163840 unique pair rows
#define NPLAYER 131072
#define PD      256

// ---------------- scratch (static device globals; no runtime allocation) ----
__device__ __nv_bfloat16 g_ehi [(size_t)NPLAYER * PD];
__device__ __nv_bfloat16 g_elo [(size_t)NPLAYER * PD];
__device__ __nv_bfloat16 g_h1hi[(size_t)NROW * 512];
__device__ __nv_bfloat16 g_h1lo[(size_t)NROW * 512];
__device__ __nv_bfloat16 g_hhi [(size_t)NROW * 256];
__device__ __nv_bfloat16 g_hlo [(size_t)NROW * 256];
__device__ float         g_wh  [(size_t)NROW * 256];
__device__ float         g_o2  [(size_t)BSZ * NPAIR];
__device__ __nv_bfloat16 g_w1hi[512 * 256], g_w1lo[512 * 256];
__device__ __nv_bfloat16 g_w2hi[256 * 512], g_w2lo[256 * 512];
__device__ __nv_bfloat16 g_awhi[256 * 256], g_awlo[256 * 256];
__device__ __nv_bfloat16 g_m1hi[512 * 256], g_m1lo[512 * 256];

__constant__ int c_i1[NPAIR] = {0,0,0,0, 1,1,1,1, 2,2,2,2, 3,3,3,3, 4,4,4,4};
__constant__ int c_i2[NPAIR] = {1,2,3,4, 0,2,3,4, 0,1,3,4, 0,1,2,4, 0,1,2,3};
// unique pairs (i<j) and their two destination slots in the ordered-pair list
__constant__ int c_u1[NPAIR_U] = {0,0,0,0, 1,1,1, 2,2, 3};
__constant__ int c_u2[NPAIR_U] = {1,2,3,4, 2,3,4, 3,4, 4};
__constant__ int c_sA[NPAIR_U] = {0,1,2,3, 5,6,7, 10,11, 15};   // i*4 + (j-1)
__constant__ int c_sB[NPAIR_U] = {4,8,12,16, 9,13,17, 14,18, 19}; // j*4 + i

__device__ __forceinline__ float siluf(float x) { return x / (1.0f + __expf(-x)); }

__device__ __forceinline__ unsigned smem_u32(const void* p) {
    return (unsigned)__cvta_generic_to_shared(p);
}
__device__ __forceinline__ void ldsm_x4(uint32_t* r, unsigned addr) {
    asm volatile("ldmatrix.sync.aligned.m8n8.x4.shared.b16 {%0,%1,%2,%3}, [%4];"
                 : "=r"(r[0]), "=r"(r[1]), "=r"(r[2]), "=r"(r[3]) : "r"(addr));
}
// one x4 delivering B fragments for TWO adjacent n-tiles (k16 each)
__device__ __forceinline__ void ldsm_x4_b2(uint32_t* b0, uint32_t* b1, unsigned addr) {
    asm volatile("ldmatrix.sync.aligned.m8n8.x4.shared.b16 {%0,%1,%2,%3}, [%4];"
                 : "=r"(b0[0]), "=r"(b0[1]), "=r"(b1[0]), "=r"(b1[1]) : "r"(addr));
}
__device__ __forceinline__ void mma16816(float* c, const uint32_t* a, const uint32_t* b) {
    asm volatile(
        "mma.sync.aligned.m16n8k16.row.col.f32.bf16.bf16.f32 "
        "{%0,%1,%2,%3}, {%4,%5,%6,%7}, {%8,%9}, {%0,%1,%2,%3};"
        : "+f"(c[0]), "+f"(c[1]), "+f"(c[2]), "+f"(c[3])
        : "r"(a[0]), "r"(a[1]), "r"(a[2]), "r"(a[3]), "r"(b[0]), "r"(b[1]));
}
__device__ __forceinline__ void store_split2(__nv_bfloat16* hi, __nv_bfloat16* lo,
                                             size_t off, float y0, float y1) {
    __nv_bfloat16 h0 = __float2bfloat16(y0), h1 = __float2bfloat16(y1);
    *(__nv_bfloat162*)(hi + off) = __halves2bfloat162(h0, h1);
    *(__nv_bfloat162*)(lo + off) = __halves2bfloat162(
        __float2bfloat16(y0 - __bfloat162float(h0)),
        __float2bfloat16(y1 - __bfloat162float(h1)));
}

// ---------------------------------------------------------------------------
// Split fp32 -> (hi, lo) bf16 pair
// ---------------------------------------------------------------------------
__global__ void split_k(const float* __restrict__ s, __nv_bfloat16* __restrict__ hi,
                        __nv_bfloat16* __restrict__ lo, int n) {
    int i = blockIdx.x * 256 + threadIdx.x;
    if (i >= n) return;
    float v = s[i];
    __nv_bfloat16 h = __float2bfloat16(v);
    hi[i] = h;
    lo[i] = __float2bfloat16(v - __bfloat162float(h));
}

// ---------------------------------------------------------------------------
// Split-bf16 tensor-core GEMM:  C[M,N] = ep(A[M,K] @ W[N,K]^T + bias)
// A,W given as (hi,lo) pairs; 3 K-segments: (hi,hi),(lo,hi),(hi,lo).
// 128x128x32 block, 8 warps (2x4), m16n8k16 mma, 2-buffer pipeline.
// EP: 0 = silu + split-store   1 = split-store   2 = fp32 store
// ---------------------------------------------------------------------------
template <int K, int EP, bool GATHER>
__global__ __launch_bounds__(256)
void mma_gemm_k(const __nv_bfloat16* __restrict__ Ahi, const __nv_bfloat16* __restrict__ Alo,
                const __nv_bfloat16* __restrict__ Whi, const __nv_bfloat16* __restrict__ Wlo,
                const float* __restrict__ bias,
                __nv_bfloat16* __restrict__ Chi, __nv_bfloat16* __restrict__ Clo,
                float* __restrict__ Cf, const int* __restrict__ ids, int N)
{
    constexpr int KIT = K / 32;
    constexpr int NIT = 3 * KIT;
    __shared__ __align__(16) __nv_bfloat16 As[2][128][40];
    __shared__ __align__(16) __nv_bfloat16 Ws[2][128][40];
    __shared__ int idS[128];

    const int t = threadIdx.x;
    const int lane = t & 31, warp = t >> 5;
    const int wm = warp >> 2, wn = warp & 3;
    const int m0 = blockIdx.y * 128, n0 = blockIdx.x * 128;

    if constexpr (GATHER) {
        if (t < 128) idS[t] = ids[m0 + t];
        __syncthreads();
    }

    float acc[4][4][4];
#pragma unroll
    for (int a = 0; a < 4; a++)
#pragma unroll
        for (int b = 0; b < 4; b++)
#pragma unroll
            for (int c = 0; c < 4; c++) acc[a][b][c] = 0.f;

    const int a_mrow = ((lane >> 3) & 1) * 8 + (lane & 7);
    const int a_kc   = (lane >> 4) * 8;
    // B x4 pair-load lane mapping: 4 matrices = {nt k0, nt k1, nt+1 k0, nt+1 k1}
    const int b_nrow = ((lane >> 4) & 1) * 8 + (lane & 7);
    const int b_kc   = ((lane >> 3) & 1) * 8;

    uint4 ra[2], rw[2];
    {
        const __nv_bfloat16* pa = Ahi;
        const __nv_bfloat16* pw = Whi;
#pragma unroll
        for (int u = 0; u < 2; u++) {
            int idx = t + u * 256, row = idx >> 2, ch = (idx & 3) << 3;
            size_t arow = GATHER ? (size_t)idS[row] : (size_t)(m0 + row);
            ra[u] = *(const uint4*)(pa + arow * K + ch);
            rw[u] = *(const uint4*)(pw + (size_t)(n0 + row) * K + ch);
        }
    }

    int buf = 0;
    for (int it = 0; it < NIT; it++) {
#pragma unroll
        for (int u = 0; u < 2; u++) {
            int idx = t + u * 256, row = idx >> 2, ch = (idx & 3) << 3;
            *(uint4*)&As[buf][row][ch] = ra[u];
            *(uint4*)&Ws[buf][row][ch] = rw[u];
        }
        __syncthreads();
        if (it + 1 < NIT) {
            int seg = (it + 1) / KIT, kk = ((it + 1) % KIT) * 32;
            const __nv_bfloat16* pa = (seg == 1) ? Alo : Ahi;
            const __nv_bfloat16* pw = (seg == 2) ? Wlo : Whi;
#pragma unroll
            for (int u = 0; u < 2; u++) {
                int idx = t + u * 256, row = idx >> 2, ch = (idx & 3) << 3;
                size_t arow = GATHER ? (size_t)idS[row] : (size_t)(m0 + row);
                ra[u] = *(const uint4*)(pa + arow * K + kk + ch);
                rw[u] = *(const uint4*)(pw + (size_t)(n0 + row) * K + kk + ch);
            }
        }
        unsigned aB = smem_u32(&As[buf][0][0]);
        unsigned wB = smem_u32(&Ws[buf][0][0]);
#pragma unroll
        for (int ks = 0; ks < 2; ks++) {
            uint32_t bfrg[4][2];
#pragma unroll
            for (int ntp = 0; ntp < 2; ntp++)
                ldsm_x4_b2(bfrg[2 * ntp], bfrg[2 * ntp + 1],
                           wB + 2u * ((wn * 32 + ntp * 16 + b_nrow) * 40 + ks * 16 + b_kc));
#pragma unroll
            for (int mt = 0; mt < 4; mt++) {
                uint32_t af[4];
                ldsm_x4(af, aB + 2u * ((wm * 64 + mt * 16 + a_mrow) * 40 + ks * 16 + a_kc));
#pragma unroll
                for (int nt = 0; nt < 4; nt++) mma16816(acc[mt][nt], af, bfrg[nt]);
            }
        }
        buf ^= 1;
    }

    // epilogue
#pragma unroll
    for (int mt = 0; mt < 4; mt++)
#pragma unroll
        for (int nt = 0; nt < 4; nt++) {
            int row = m0 + wm * 64 + mt * 16 + (lane >> 2);
            int col = n0 + wn * 32 + nt * 8 + ((lane & 3) << 1);
            float2 bz = *(const float2*)(bias + col);
            float* c = acc[mt][nt];
            float y0 = c[0] + bz.x, y1 = c[1] + bz.y;
            float y2 = c[2] + bz.x, y3 = c[3] + bz.y;
            if (EP == 0) { y0 = siluf(y0); y1 = siluf(y1); y2 = siluf(y2); y3 = siluf(y3); }
            if (EP <= 1) {
                store_split2(Chi, Clo, (size_t)row * N + col, y0, y1);
                store_split2(Chi, Clo, (size_t)(row + 8) * N + col, y2, y3);
            } else {
                *(float2*)(Cf + (size_t)row * N + col)       = make_float2(y0, y1);
                *(float2*)(Cf + (size_t)(row + 8) * N + col) = make_float2(y2, y3);
            }
        }
}

// ---------------------------------------------------------------------------
// Pair-MLP kernel over UNIQUE pairs (prod symmetric => order2(i,j)==order2(j,i)).
// A row = h[b,i] ⊙ h[b,j], i<j, built once per block (hi/lo split) into
// smem-resident tiles; W streamed; 3-way split mma; epilogue folds
// silu(+b1)·w2 into per-row scalars, scattered to BOTH ordered slots of O2.
// ---------------------------------------------------------------------------
#define PAIRS_SMEM (2 * 128 * 264 * 2 + 2 * 2 * 128 * 40 * 2 + 256 * 4 + 512 * 4)

__global__ __launch_bounds__(256)
void pairs_mma_k(const __nv_bfloat16* __restrict__ Hhi, const __nv_bfloat16* __restrict__ Hlo,
                 const __nv_bfloat16* __restrict__ W1hi, const __nv_bfloat16* __restrict__ W1lo,
                 const float* __restrict__ b1, const float* __restrict__ w2,
                 float* __restrict__ O2)
{
    extern __shared__ __align__(16) char smraw[];
    __nv_bfloat16* Aphi = (__nv_bfloat16*)smraw;            // [128][264]
    __nv_bfloat16* Aplo = Aphi + 128 * 264;                 // [128][264]
    __nv_bfloat16* Wt   = Aplo + 128 * 264;                 // [2 buf][2 hl][128][40]
    int*   off1s = (int*)(Wt + 2 * 2 * 128 * 40);
    int*   off2s = off1s + 128;
    float* redS  = (float*)(off2s + 128);                   // [4][128]

    const int t = threadIdx.x, lane = t & 31, warp = t >> 5;
    const int wm = warp >> 2, wn = warp & 3;
    const int m0 = blockIdx.x * 128;

    if (t < 128) {
        int r = m0 + t, b = r / NPAIR_U, p = r - b * NPAIR_U;
        off1s[t] = (b * TEAMN + c_u1[p]) * 256;
        off2s[t] = (b * TEAMN + c_u2[p]) * 256;
    }
    __syncthreads();

    // ---- phase 1: build product tiles (hi/lo) ----
    {
        int cidx = t;
#pragma unroll 4
        for (int i = 0; i < 16; i++, cidx += 256) {
            int row = cidx >> 5;
            int ch  = (cidx & 31) << 3;
            int o1 = off1s[row] + ch, o2 = off2s[row] + ch;
            uint4 u1h = *(const uint4*)(Hhi + o1);
            uint4 u1l = *(const uint4*)(Hlo + o1);
            uint4 u2h = *(const uint4*)(Hhi + o2);
            uint4 u2l = *(const uint4*)(Hlo + o2);
            const __nv_bfloat162* p1h = (const __nv_bfloat162*)&u1h;
            const __nv_bfloat162* p1l = (const __nv_bfloat162*)&u1l;
            const __nv_bfloat162* p2h = (const __nv_bfloat162*)&u2h;
            const __nv_bfloat162* p2l = (const __nv_bfloat162*)&u2l;
            __nv_bfloat162 oph[4], opl[4];
#pragma unroll
            for (int j = 0; j < 4; j++) {
                float2 a  = __bfloat1622float2(p1h[j]);
                float2 al = __bfloat1622float2(p1l[j]);
                float2 b_ = __bfloat1622float2(p2h[j]);
                float2 bl_ = __bfloat1622float2(p2l[j]);
                float f0 = (a.x + al.x) * (b_.x + bl_.x);
                float f1 = (a.y + al.y) * (b_.y + bl_.y);
                __nv_bfloat16 h0 = __float2bfloat16(f0), h1 = __float2bfloat16(f1);
                oph[j] = __halves2bfloat162(h0, h1);
                opl[j] = __halves2bfloat162(
                    __float2bfloat16(f0 - __bfloat162float(h0)),
                    __float2bfloat16(f1 - __bfloat162float(h1)));
            }
            *(uint4*)(Aphi + row * 264 + ch) = *(uint4*)oph;
            *(uint4*)(Aplo + row * 264 + ch) = *(uint4*)opl;
        }
    }

    float rowsum[4][2];
#pragma unroll
    for (int a = 0; a < 4; a++) { rowsum[a][0] = 0.f; rowsum[a][1] = 0.f; }

    const int a_mrow = ((lane >> 3) & 1) * 8 + (lane & 7);
    const int a_kc   = (lane >> 4) * 8;
    const int b_nrow = ((lane >> 4) & 1) * 8 + (lane & 7);
    const int b_kc   = ((lane >> 3) & 1) * 8;
    const unsigned aPhiB = smem_u32(Aphi);
    const unsigned aPloB = smem_u32(Aplo);
    const unsigned wB    = smem_u32(Wt);

    uint4 rwh[2], rwl[2];
#pragma unroll
    for (int u = 0; u < 2; u++) {    // prefetch n0=0, k0=0
        int idx = t + u * 256, row = idx >> 2, ch = (idx & 3) << 3;
        size_t go = (size_t)row * 256 + ch;
        rwh[u] = *(const uint4*)(W1hi + go);
        rwl[u] = *(const uint4*)(W1lo + go);
    }

    int buf = 0;
    for (int n0i = 0; n0i < 4; n0i++) {
        int n0 = n0i * 128;
        float acc[4][4][4];
#pragma unroll
        for (int a = 0; a < 4; a++)
#pragma unroll
            for (int b = 0; b < 4; b++)
#pragma unroll
                for (int c = 0; c < 4; c++) acc[a][b][c] = 0.f;

        for (int k0 = 0; k0 < 8; k0++) {
#pragma unroll
            for (int u = 0; u < 2; u++) {
                int idx = t + u * 256, row = idx >> 2, ch = (idx & 3) << 3;
                *(uint4*)(Wt + (buf * 2 + 0) * 5120 + row * 40 + ch) = rwh[u];
                *(uint4*)(Wt + (buf * 2 + 1) * 5120 + row * 40 + ch) = rwl[u];
            }
            __syncthreads();
            if (!(n0i == 3 && k0 == 7)) {
                int nk = k0 + 1, nn = n0i;
                if (nk == 8) { nk = 0; nn++; }
#pragma unroll
                for (int u = 0; u < 2; u++) {
                    int idx = t + u * 256, row = idx >> 2, ch = (idx & 3) << 3;
                    size_t go = (size_t)(nn * 128 + row) * 256 + nk * 32 + ch;
                    rwh[u] = *(const uint4*)(W1hi + go);
                    rwl[u] = *(const uint4*)(W1lo + go);
                }
            }
#pragma unroll
            for (int ks = 0; ks < 2; ks++) {
                int kpos = k0 * 32 + ks * 16;
                uint32_t bh[4][2], blo_[4][2];
#pragma unroll
                for (int ntp = 0; ntp < 2; ntp++) {
                    unsigned wo = (wn * 32 + ntp * 16 + b_nrow) * 40 + ks * 16 + b_kc;
                    ldsm_x4_b2(bh[2 * ntp],   bh[2 * ntp + 1],
                               wB + 2u * ((buf * 2 + 0) * 5120 + wo));
                    ldsm_x4_b2(blo_[2 * ntp], blo_[2 * ntp + 1],
                               wB + 2u * ((buf * 2 + 1) * 5120 + wo));
                }
#pragma unroll
                for (int mt = 0; mt < 4; mt++) {
                    unsigned ao = (wm * 64 + mt * 16 + a_mrow) * 264 + kpos + a_kc;
                    uint32_t af[4];
                    ldsm_x4(af, aPhiB + 2u * ao);
#pragma unroll
                    for (int nt = 0; nt < 4; nt++) mma16816(acc[mt][nt], af, bh[nt]);
#pragma unroll
                    for (int nt = 0; nt < 4; nt++) mma16816(acc[mt][nt], af, blo_[nt]);
                    ldsm_x4(af, aPloB + 2u * ao);
#pragma unroll
                    for (int nt = 0; nt < 4; nt++) mma16816(acc[mt][nt], af, bh[nt]);
                }
            }
            buf ^= 1;
        }
        // fold this n-chunk into rowsums
#pragma unroll
        for (int mt = 0; mt < 4; mt++)
#pragma unroll
            for (int nt = 0; nt < 4; nt++) {
                int col = n0 + wn * 32 + nt * 8 + ((lane & 3) << 1);
                float2 bz = *(const float2*)(b1 + col);
                float2 wz = *(const float2*)(w2 + col);
                float* c = acc[mt][nt];
                rowsum[mt][0] += siluf(c[0] + bz.x) * wz.x + siluf(c[1] + bz.y) * wz.y;
                rowsum[mt][1] += siluf(c[2] + bz.x) * wz.x + siluf(c[3] + bz.y) * wz.y;
            }
    }

    // reduce over the 4 lanes sharing a row, then across the 4 n-warps
#pragma unroll
    for (int mt = 0; mt < 4; mt++)
#pragma unroll
        for (int p = 0; p < 2; p++) {
            float v = rowsum[mt][p];
            v += __shfl_xor_sync(0xffffffffu, v, 1);
            v += __shfl_xor_sync(0xffffffffu, v, 2);
            rowsum[mt][p] = v;
        }
    __syncthreads();
    if ((lane & 3) == 0) {
#pragma unroll
        for (int mt = 0; mt < 4; mt++)
#pragma unroll
            for (int p = 0; p < 2; p++) {
                int r = wm * 64 + mt * 16 + (lane >> 2) + p * 8;
                redS[wn * 128 + r] = rowsum[mt][p];
            }
    }
    __syncthreads();
    if (t < 128) {
        float v = redS[t] + redS[128 + t] + redS[256 + t] + redS[384 + t];
        int r = m0 + t, b = r / NPAIR_U, p = r - b * NPAIR_U;
        O2[b * NPAIR + c_sA[p]] = v;   // (i,j)
        O2[b * NPAIR + c_sB[p]] = v;   // (j,i) — identical by symmetry
    }
}

// ---------------------------------------------------------------------------
// Final: score[p] = <wh[b,i1], h[b,i2]>, softmax per group-of-4, weighted sum.
// ---------------------------------------------------------------------------
__global__ __launch_bounds__(128)
void final_k(const __nv_bfloat16* __restrict__ Hhi, const __nv_bfloat16* __restrict__ Hlo,
             const float* __restrict__ WH, const float* __restrict__ O2,
             const float* __restrict__ mlp_b2, float* __restrict__ out)
{
    __shared__ float scoreS[4][NPAIR];
    const int wi = threadIdx.x >> 5, lane = threadIdx.x & 31;
    const int b = blockIdx.x * 4 + wi;
    const __nv_bfloat16* hbh = Hhi + (size_t)b * TEAMN * 256;
    const __nv_bfloat16* hbl = Hlo + (size_t)b * TEAMN * 256;
    const float* whb = WH + (size_t)b * TEAMN * 256;

    for (int p = 0; p < NPAIR; p++) {
        const float* wa = whb + c_i1[p] * 256;
        int ho = c_i2[p] * 256 + lane * 8;
        uint4 uh = *(const uint4*)(hbh + ho);
        uint4 ul = *(const uint4*)(hbl + ho);
        const __nv_bfloat162* ph = (const __nv_bfloat162*)&uh;
        const __nv_bfloat162* pl = (const __nv_bfloat162*)&ul;
        float xv[8];
        *(float4*)&xv[0] = *(const float4*)(wa + lane * 8);
        *(float4*)&xv[4] = *(const float4*)(wa + lane * 8 + 4);
        float s = 0.f;
#pragma unroll
        for (int j = 0; j < 4; j++) {
            float2 hh = __bfloat1622float2(ph[j]);
            float2 hl = __bfloat1622float2(pl[j]);
            s += xv[2 * j] * (hh.x + hl.x) + xv[2 * j + 1] * (hh.y + hl.y);
        }
#pragma unroll
        for (int off = 16; off > 0; off >>= 1)
            s += __shfl_down_sync(0xffffffffu, s, off);
        if (lane == 0) scoreS[wi][p] = s;
    }
    __syncwarp();

    float partial = 0.f;
    if (lane < TEAMN) {
        float sc[4];
#pragma unroll
        for (int j = 0; j < 4; j++) sc[j] = scoreS[wi][lane * 4 + j];
        float mx = fmaxf(fmaxf(sc[0], sc[1]), fmaxf(sc[2], sc[3]));
        float e[4], se = 0.f;
#pragma unroll
        for (int j = 0; j < 4; j++) { e[j] = __expf(sc[j] - mx); se += e[j]; }
        float bias2 = mlp_b2[0];
        float acc = 0.f;
#pragma unroll
        for (int j = 0; j < 4; j++)
            acc += e[j] * (O2[b * NPAIR + lane * 4 + j] + bias2);
        partial = acc / se;
    }
#pragma unroll
    for (int off = 16; off > 0; off >>= 1)
        partial += __shfl_down_sync(0xffffffffu, partial, off);
    if (lane == 0) out[b] = partial;
}

// ---------------------------------------------------------------------------
extern "C" void kernel_launch(void* const* d_in, const int* in_sizes, int n_in,
                              void* d_out, int out_size)
{
    const int*   team_ids = (const int*)  d_in[0];
    const float* emb      = (const float*)d_in[1];
    const float* fm_w1    = (const float*)d_in[2];
    const float* fm_b1    = (const float*)d_in[3];
    const float* fm_w2    = (const float*)d_in[4];
    const float* fm_b2    = (const float*)d_in[5];
    const float* att_w    = (const float*)d_in[6];
    const float* att_b    = (const float*)d_in[7];
    const float* mlp_w1   = (const float*)d_in[8];
    const float* mlp_b1   = (const float*)d_in[9];
    const float* mlp_w2   = (const float*)d_in[10];
    const float* mlp_b2   = (const float*)d_in[11];
    float* out = (float*)d_out;

    void *p_ehi, *p_elo, *p_h1hi, *p_h1lo, *p_hhi, *p_hlo, *p_wh, *p_o2;
    void *p_w1hi, *p_w1lo, *p_w2hi, *p_w2lo, *p_awhi, *p_awlo, *p_m1hi, *p_m1lo;
    cudaGetSymbolAddress(&p_ehi,  g_ehi);  cudaGetSymbolAddress(&p_elo,  g_elo);
    cudaGetSymbolAddress(&p_h1hi, g_h1hi); cudaGetSymbolAddress(&p_h1lo, g_h1lo);
    cudaGetSymbolAddress(&p_hhi,  g_hhi);  cudaGetSymbolAddress(&p_hlo,  g_hlo);
    cudaGetSymbolAddress(&p_wh,   g_wh);   cudaGetSymbolAddress(&p_o2,   g_o2);
    cudaGetSymbolAddress(&p_w1hi, g_w1hi); cudaGetSymbolAddress(&p_w1lo, g_w1lo);
    cudaGetSymbolAddress(&p_w2hi, g_w2hi); cudaGetSymbolAddress(&p_w2lo, g_w2lo);
    cudaGetSymbolAddress(&p_awhi, g_awhi); cudaGetSymbolAddress(&p_awlo, g_awlo);
    cudaGetSymbolAddress(&p_m1hi, g_m1hi); cudaGetSymbolAddress(&p_m1lo, g_m1lo);

    // split fp32 -> hi/lo bf16
    {
        int n = NPLAYER * PD;
        split_k<<<(n + 255) / 256, 256>>>(emb, (__nv_bfloat16*)p_ehi, (__nv_bfloat16*)p_elo, n);
    }
    split_k<<<(512 * 256 + 255) / 256, 256>>>(fm_w1,  (__nv_bfloat16*)p_w1hi, (__nv_bfloat16*)p_w1lo, 512 * 256);
    split_k<<<(256 * 512 + 255) / 256, 256>>>(fm_w2,  (__nv_bfloat16*)p_w2hi, (__nv_bfloat16*)p_w2lo, 256 * 512);
    split_k<<<(256 * 256 + 255) / 256, 256>>>(att_w,  (__nv_bfloat16*)p_awhi, (__nv_bfloat16*)p_awlo, 256 * 256);
    split_k<<<(512 * 256 + 255) / 256, 256>>>(mlp_w1, (__nv_bfloat16*)p_m1hi, (__nv_bfloat16*)p_m1lo, 512 * 256);

    // fm1: gather + silu(x @ fm_w1^T + b1) -> h1 (hi/lo)
    mma_gemm_k<256, 0, true><<<dim3(4, NROW / 128), 256>>>(
        (const __nv_bfloat16*)p_ehi, (const __nv_bfloat16*)p_elo,
        (const __nv_bfloat16*)p_w1hi, (const __nv_bfloat16*)p_w1lo,
        fm_b1, (__nv_bfloat16*)p_h1hi, (__nv_bfloat16*)p_h1lo, nullptr, team_ids, 512);
    // fm2: h1 @ fm_w2^T + b2 -> h (hi/lo)
    mma_gemm_k<512, 1, false><<<dim3(2, NROW / 128), 256>>>(
        (const __nv_bfloat16*)p_h1hi, (const __nv_bfloat16*)p_h1lo,
        (const __nv_bfloat16*)p_w2hi, (const __nv_bfloat16*)p_w2lo,
        fm_b2, (__nv_bfloat16*)p_hhi, (__nv_bfloat16*)p_hlo, nullptr, nullptr, 256);
    // att (hoisted per member): h @ att_w^T + att_b -> wh (fp32)
    mma_gemm_k<256, 2, false><<<dim3(2, NROW / 128), 256>>>(
        (const __nv_bfloat16*)p_hhi, (const __nv_bfloat16*)p_hlo,
        (const __nv_bfloat16*)p_awhi, (const __nv_bfloat16*)p_awlo,
        att_b, nullptr, nullptr, (float*)p_wh, nullptr, 256);
    // pair MLP over unique pairs + order2 scatter -> o2
    cudaFuncSetAttribute(pairs_mma_k, cudaFuncAttributeMaxDynamicSharedMemorySize, PAIRS_SMEM);
    pairs_mma_k<<<MROW_U / 128, 256, PAIRS_SMEM>>>(
        (const __nv_bfloat16*)p_hhi, (const __nv_bfloat16*)p_hlo,
        (const __nv_bfloat16*)p_m1hi, (const __nv_bfloat16*)p_m1lo,
        mlp_b1, mlp_w2, (float*)p_o2);
    // scores + softmax + weighted sum
    final_k<<<BSZ / 4, 128>>>(
        (const __nv_bfloat16*)p_hhi, (const __nv_bfloat16*)p_hlo,
        (const float*)p_wh, (const float*)p_o2, mlp_b2, out);
}

// round 9
// speedup vs baseline: 3.2757x; 1.0572x over previous
#include <cuda_runtime.h>
#include <cuda_bf16.h>
#include <cstdint>

#define TEAMN   5
#define BSZ     16384
#define NROW    (BSZ * TEAMN)     // 81920 member rows
#define NPAIR   20
#define NPAIR_U 10                // unique unordered pairs (prod is symmetric)
#define MROW_U  (BSZ * NPAIR_U)   // 163840 unique pair rows
#define NPLAYER 131072
#define PD      256

// ---------------- scratch (static device globals; no runtime allocation) ----
__device__ __nv_bfloat16 g_h1hi[(size_t)NROW * 512];
__device__ __nv_bfloat16 g_h1lo[(size_t)NROW * 512];
__device__ __nv_bfloat16 g_hhi [(size_t)NROW * 256];
__device__ __nv_bfloat16 g_hlo [(size_t)NROW * 256];
__device__ float         g_wh  [(size_t)NROW * 256];
__device__ float         g_o2  [(size_t)BSZ * NPAIR];
__device__ __nv_bfloat16 g_w1hi[512 * 256], g_w1lo[512 * 256];
__device__ __nv_bfloat16 g_w2hi[256 * 512], g_w2lo[256 * 512];
__device__ __nv_bfloat16 g_awhi[256 * 256], g_awlo[256 * 256];
__device__ __nv_bfloat16 g_m1hi[512 * 256], g_m1lo[512 * 256];

__constant__ int c_i1[NPAIR] = {0,0,0,0, 1,1,1,1, 2,2,2,2, 3,3,3,3, 4,4,4,4};
__constant__ int c_i2[NPAIR] = {1,2,3,4, 0,2,3,4, 0,1,3,4, 0,1,2,4, 0,1,2,3};
__constant__ int c_u1[NPAIR_U] = {0,0,0,0, 1,1,1, 2,2, 3};
__constant__ int c_u2[NPAIR_U] = {1,2,3,4, 2,3,4, 3,4, 4};
__constant__ int c_sA[NPAIR_U] = {0,1,2,3, 5,6,7, 10,11, 15};
__constant__ int c_sB[NPAIR_U] = {4,8,12,16, 9,13,17, 14,18, 19};

__device__ __forceinline__ float siluf(float x) { return x / (1.0f + __expf(-x)); }

__device__ __forceinline__ unsigned smem_u32(const void* p) {
    return (unsigned)__cvta_generic_to_shared(p);
}
__device__ __forceinline__ void ldsm_x4(uint32_t* r, unsigned addr) {
    asm volatile("ldmatrix.sync.aligned.m8n8.x4.shared.b16 {%0,%1,%2,%3}, [%4];"
                 : "=r"(r[0]), "=r"(r[1]), "=r"(r[2]), "=r"(r[3]) : "r"(addr));
}
// one x4 delivering B fragments for TWO adjacent n-tiles (k16 each)
__device__ __forceinline__ void ldsm_x4_b2(uint32_t* b0, uint32_t* b1, unsigned addr) {
    asm volatile("ldmatrix.sync.aligned.m8n8.x4.shared.b16 {%0,%1,%2,%3}, [%4];"
                 : "=r"(b0[0]), "=r"(b0[1]), "=r"(b1[0]), "=r"(b1[1]) : "r"(addr));
}
__device__ __forceinline__ void mma16816(float* c, const uint32_t* a, const uint32_t* b) {
    asm volatile(
        "mma.sync.aligned.m16n8k16.row.col.f32.bf16.bf16.f32 "
        "{%0,%1,%2,%3}, {%4,%5,%6,%7}, {%8,%9}, {%0,%1,%2,%3};"
        : "+f"(c[0]), "+f"(c[1]), "+f"(c[2]), "+f"(c[3])
        : "r"(a[0]), "r"(a[1]), "r"(a[2]), "r"(a[3]), "r"(b[0]), "r"(b[1]));
}
__device__ __forceinline__ void store_split2(__nv_bfloat16* hi, __nv_bfloat16* lo,
                                             size_t off, float y0, float y1) {
    __nv_bfloat16 h0 = __float2bfloat16(y0), h1 = __float2bfloat16(y1);
    *(__nv_bfloat162*)(hi + off) = __halves2bfloat162(h0, h1);
    *(__nv_bfloat162*)(lo + off) = __halves2bfloat162(
        __float2bfloat16(y0 - __bfloat162float(h0)),
        __float2bfloat16(y1 - __bfloat162float(h1)));
}

// ---------------------------------------------------------------------------
// Combined weight split: fm_w1, fm_w2, att_w, mlp_w1 -> (hi, lo) bf16 pairs
// in ONE launch (ranges concatenated).
// ---------------------------------------------------------------------------
#define W1_N 131072            // 512*256
#define W2_N 131072            // 256*512
#define AW_N 65536             // 256*256
#define M1_N 131072            // 512*256
#define WTOT (W1_N + W2_N + AW_N + M1_N)   // 458752

__global__ void splitw_k(const float* __restrict__ w1, const float* __restrict__ w2,
                         const float* __restrict__ aw, const float* __restrict__ m1,
                         __nv_bfloat16* __restrict__ w1h, __nv_bfloat16* __restrict__ w1l,
                         __nv_bfloat16* __restrict__ w2h, __nv_bfloat16* __restrict__ w2l,
                         __nv_bfloat16* __restrict__ awh, __nv_bfloat16* __restrict__ awl,
                         __nv_bfloat16* __restrict__ m1h, __nv_bfloat16* __restrict__ m1l)
{
    int i = blockIdx.x * 256 + threadIdx.x;
    if (i >= WTOT) return;
    const float* s; __nv_bfloat16 *hi, *lo; int j = i;
    if (j < W1_N)                { s = w1; hi = w1h; lo = w1l; }
    else if ((j -= W1_N) < W2_N) { s = w2; hi = w2h; lo = w2l; }
    else if ((j -= W2_N) < AW_N) { s = aw; hi = awh; lo = awl; }
    else { j -= AW_N;              s = m1; hi = m1h; lo = m1l; }
    float v = s[j];
    __nv_bfloat16 h = __float2bfloat16(v);
    hi[j] = h;
    lo[j] = __float2bfloat16(v - __bfloat162float(h));
}

// ---------------------------------------------------------------------------
// Split-bf16 tensor-core GEMM:  C[M,N] = ep(A[M,K] @ W[N,K]^T + bias)
// 3 K-segments: (Ahi,Whi),(Alo,Whi),(Ahi,Wlo).
// 128x128x32 block, 8 warps (2x4), m16n8k16 mma, 2-buffer, 1-sync pipeline.
// GATHER: A = fp32 rows of Af gathered via ids, hi/lo computed in registers
//         at SMEM-store time (split(gather(x)) == gather(split(x))).
// EP: 0 = silu + split-store   1 = split-store   2 = fp32 store
// ---------------------------------------------------------------------------
template <int K, int EP, bool GATHER>
__global__ __launch_bounds__(256)
void mma_gemm_k(const float* __restrict__ Af,
                const __nv_bfloat16* __restrict__ Ahi, const __nv_bfloat16* __restrict__ Alo,
                const __nv_bfloat16* __restrict__ Whi, const __nv_bfloat16* __restrict__ Wlo,
                const float* __restrict__ bias,
                __nv_bfloat16* __restrict__ Chi, __nv_bfloat16* __restrict__ Clo,
                float* __restrict__ Cf, const int* __restrict__ ids, int N)
{
    constexpr int KIT = K / 32;
    constexpr int NIT = 3 * KIT;
    __shared__ __align__(16) __nv_bfloat16 As[2][128][40];
    __shared__ __align__(16) __nv_bfloat16 Ws[2][128][40];
    __shared__ int idS[128];

    const int t = threadIdx.x;
    const int lane = t & 31, warp = t >> 5;
    const int wm = warp >> 2, wn = warp & 3;
    const int m0 = blockIdx.y * 128, n0 = blockIdx.x * 128;

    if constexpr (GATHER) {
        if (t < 128) idS[t] = ids[m0 + t];
        __syncthreads();
    }

    float acc[4][4][4];
#pragma unroll
    for (int a = 0; a < 4; a++)
#pragma unroll
        for (int b = 0; b < 4; b++)
#pragma unroll
            for (int c = 0; c < 4; c++) acc[a][b][c] = 0.f;

    const int a_mrow = ((lane >> 3) & 1) * 8 + (lane & 7);
    const int a_kc   = (lane >> 4) * 8;
    const int b_nrow = ((lane >> 4) & 1) * 8 + (lane & 7);
    const int b_kc   = ((lane >> 3) & 1) * 8;

    float4 rf[4];        // GATHER: fp32 A prefetch (8 floats per u)
    uint4  ra[2];        // non-GATHER: bf16 A prefetch
    uint4  rw[2];
    // prologue fetch it=0
    {
#pragma unroll
        for (int u = 0; u < 2; u++) {
            int idx = t + u * 256, row = idx >> 2, ch = (idx & 3) << 3;
            if constexpr (GATHER) {
                const float* s = Af + (size_t)idS[row] * K + ch;
                rf[2 * u]     = *(const float4*)s;
                rf[2 * u + 1] = *(const float4*)(s + 4);
            } else {
                ra[u] = *(const uint4*)(Ahi + (size_t)(m0 + row) * K + ch);
            }
            rw[u] = *(const uint4*)(Whi + (size_t)(n0 + row) * K + ch);
        }
    }

    int buf = 0;
    for (int it = 0; it < NIT; it++) {
        const int seg = it / KIT;
#pragma unroll
        for (int u = 0; u < 2; u++) {
            int idx = t + u * 256, row = idx >> 2, ch = (idx & 3) << 3;
            if constexpr (GATHER) {
                const float* f = (const float*)&rf[2 * u];
                __nv_bfloat16 v[8];
#pragma unroll
                for (int j = 0; j < 8; j++) {
                    __nv_bfloat16 h = __float2bfloat16(f[j]);
                    v[j] = (seg == 1) ? __float2bfloat16(f[j] - __bfloat162float(h)) : h;
                }
                *(uint4*)&As[buf][row][ch] = *(uint4*)v;
            } else {
                *(uint4*)&As[buf][row][ch] = ra[u];
            }
            *(uint4*)&Ws[buf][row][ch] = rw[u];
        }
        __syncthreads();
        if (it + 1 < NIT) {
            int seg2 = (it + 1) / KIT, kk = ((it + 1) % KIT) * 32;
            const __nv_bfloat16* pw = (seg2 == 2) ? Wlo : Whi;
#pragma unroll
            for (int u = 0; u < 2; u++) {
                int idx = t + u * 256, row = idx >> 2, ch = (idx & 3) << 3;
                if constexpr (GATHER) {
                    const float* s = Af + (size_t)idS[row] * K + kk + ch;
                    rf[2 * u]     = *(const float4*)s;
                    rf[2 * u + 1] = *(const float4*)(s + 4);
                } else {
                    const __nv_bfloat16* pa = (seg2 == 1) ? Alo : Ahi;
                    ra[u] = *(const uint4*)(pa + (size_t)(m0 + row) * K + kk + ch);
                }
                rw[u] = *(const uint4*)(pw + (size_t)(n0 + row) * K + kk + ch);
            }
        }
        unsigned aB = smem_u32(&As[buf][0][0]);
        unsigned wB = smem_u32(&Ws[buf][0][0]);
#pragma unroll
        for (int ks = 0; ks < 2; ks++) {
            uint32_t bfrg[4][2];
#pragma unroll
            for (int ntp = 0; ntp < 2; ntp++)
                ldsm_x4_b2(bfrg[2 * ntp], bfrg[2 * ntp + 1],
                           wB + 2u * ((wn * 32 + ntp * 16 + b_nrow) * 40 + ks * 16 + b_kc));
#pragma unroll
            for (int mt = 0; mt < 4; mt++) {
                uint32_t af[4];
                ldsm_x4(af, aB + 2u * ((wm * 64 + mt * 16 + a_mrow) * 40 + ks * 16 + a_kc));
#pragma unroll
                for (int nt = 0; nt < 4; nt++) mma16816(acc[mt][nt], af, bfrg[nt]);
            }
        }
        buf ^= 1;
    }

    // epilogue
#pragma unroll
    for (int mt = 0; mt < 4; mt++)
#pragma unroll
        for (int nt = 0; nt < 4; nt++) {
            int row = m0 + wm * 64 + mt * 16 + (lane >> 2);
            int col = n0 + wn * 32 + nt * 8 + ((lane & 3) << 1);
            float2 bz = *(const float2*)(bias + col);
            float* c = acc[mt][nt];
            float y0 = c[0] + bz.x, y1 = c[1] + bz.y;
            float y2 = c[2] + bz.x, y3 = c[3] + bz.y;
            if (EP == 0) { y0 = siluf(y0); y1 = siluf(y1); y2 = siluf(y2); y3 = siluf(y3); }
            if (EP <= 1) {
                store_split2(Chi, Clo, (size_t)row * N + col, y0, y1);
                store_split2(Chi, Clo, (size_t)(row + 8) * N + col, y2, y3);
            } else {
                *(float2*)(Cf + (size_t)row * N + col)       = make_float2(y0, y1);
                *(float2*)(Cf + (size_t)(row + 8) * N + col) = make_float2(y2, y3);
            }
        }
}

// ---------------------------------------------------------------------------
// Pair-MLP kernel over UNIQUE pairs (prod symmetric => order2(i,j)==order2(j,i)).
// A row = h[b,i] ⊙ h[b,j], i<j, built once per block (hi/lo split) into
// smem-resident tiles; W streamed; 3-way split mma; epilogue folds
// silu(+b1)·w2 into per-row scalars, scattered to BOTH ordered slots of O2.
// ---------------------------------------------------------------------------
#define PAIRS_SMEM (2 * 128 * 264 * 2 + 2 * 2 * 128 * 40 * 2 + 256 * 4 + 512 * 4)

__global__ __launch_bounds__(256)
void pairs_mma_k(const __nv_bfloat16* __restrict__ Hhi, const __nv_bfloat16* __restrict__ Hlo,
                 const __nv_bfloat16* __restrict__ W1hi, const __nv_bfloat16* __restrict__ W1lo,
                 const float* __restrict__ b1, const float* __restrict__ w2,
                 float* __restrict__ O2)
{
    extern __shared__ __align__(16) char smraw[];
    __nv_bfloat16* Aphi = (__nv_bfloat16*)smraw;            // [128][264]
    __nv_bfloat16* Aplo = Aphi + 128 * 264;                 // [128][264]
    __nv_bfloat16* Wt   = Aplo + 128 * 264;                 // [2 buf][2 hl][128][40]
    int*   off1s = (int*)(Wt + 2 * 2 * 128 * 40);
    int*   off2s = off1s + 128;
    float* redS  = (float*)(off2s + 128);                   // [4][128]

    const int t = threadIdx.x, lane = t & 31, warp = t >> 5;
    const int wm = warp >> 2, wn = warp & 3;
    const int m0 = blockIdx.x * 128;

    if (t < 128) {
        int r = m0 + t, b = r / NPAIR_U, p = r - b * NPAIR_U;
        off1s[t] = (b * TEAMN + c_u1[p]) * 256;
        off2s[t] = (b * TEAMN + c_u2[p]) * 256;
    }
    __syncthreads();

    // ---- phase 1: build product tiles (hi/lo) ----
    {
        int cidx = t;
#pragma unroll 4
        for (int i = 0; i < 16; i++, cidx += 256) {
            int row = cidx >> 5;
            int ch  = (cidx & 31) << 3;
            int o1 = off1s[row] + ch, o2 = off2s[row] + ch;
            uint4 u1h = *(const uint4*)(Hhi + o1);
            uint4 u1l = *(const uint4*)(Hlo + o1);
            uint4 u2h = *(const uint4*)(Hhi + o2);
            uint4 u2l = *(const uint4*)(Hlo + o2);
            const __nv_bfloat162* p1h = (const __nv_bfloat162*)&u1h;
            const __nv_bfloat162* p1l = (const __nv_bfloat162*)&u1l;
            const __nv_bfloat162* p2h = (const __nv_bfloat162*)&u2h;
            const __nv_bfloat162* p2l = (const __nv_bfloat162*)&u2l;
            __nv_bfloat162 oph[4], opl[4];
#pragma unroll
            for (int j = 0; j < 4; j++) {
                float2 a   = __bfloat1622float2(p1h[j]);
                float2 al  = __bfloat1622float2(p1l[j]);
                float2 b_  = __bfloat1622float2(p2h[j]);
                float2 bl_ = __bfloat1622float2(p2l[j]);
                float f0 = (a.x + al.x) * (b_.x + bl_.x);
                float f1 = (a.y + al.y) * (b_.y + bl_.y);
                __nv_bfloat16 h0 = __float2bfloat16(f0), h1 = __float2bfloat16(f1);
                oph[j] = __halves2bfloat162(h0, h1);
                opl[j] = __halves2bfloat162(
                    __float2bfloat16(f0 - __bfloat162float(h0)),
                    __float2bfloat16(f1 - __bfloat162float(h1)));
            }
            *(uint4*)(Aphi + row * 264 + ch) = *(uint4*)oph;
            *(uint4*)(Aplo + row * 264 + ch) = *(uint4*)opl;
        }
    }

    float rowsum[4][2];
#pragma unroll
    for (int a = 0; a < 4; a++) { rowsum[a][0] = 0.f; rowsum[a][1] = 0.f; }

    const int a_mrow = ((lane >> 3) & 1) * 8 + (lane & 7);
    const int a_kc   = (lane >> 4) * 8;
    const int b_nrow = ((lane >> 4) & 1) * 8 + (lane & 7);
    const int b_kc   = ((lane >> 3) & 1) * 8;
    const unsigned aPhiB = smem_u32(Aphi);
    const unsigned aPloB = smem_u32(Aplo);
    const unsigned wB    = smem_u32(Wt);

    uint4 rwh[2], rwl[2];
#pragma unroll
    for (int u = 0; u < 2; u++) {    // prefetch n0=0, k0=0
        int idx = t + u * 256, row = idx >> 2, ch = (idx & 3) << 3;
        size_t go = (size_t)row * 256 + ch;
        rwh[u] = *(const uint4*)(W1hi + go);
        rwl[u] = *(const uint4*)(W1lo + go);
    }

    int buf = 0;
    for (int n0i = 0; n0i < 4; n0i++) {
        int n0 = n0i * 128;
        float acc[4][4][4];
#pragma unroll
        for (int a = 0; a < 4; a++)
#pragma unroll
            for (int b = 0; b < 4; b++)
#pragma unroll
                for (int c = 0; c < 4; c++) acc[a][b][c] = 0.f;

        for (int k0 = 0; k0 < 8; k0++) {
#pragma unroll
            for (int u = 0; u < 2; u++) {
                int idx = t + u * 256, row = idx >> 2, ch = (idx & 3) << 3;
                *(uint4*)(Wt + (buf * 2 + 0) * 5120 + row * 40 + ch) = rwh[u];
                *(uint4*)(Wt + (buf * 2 + 1) * 5120 + row * 40 + ch) = rwl[u];
            }
            __syncthreads();
            if (!(n0i == 3 && k0 == 7)) {
                int nk = k0 + 1, nn = n0i;
                if (nk == 8) { nk = 0; nn++; }
#pragma unroll
                for (int u = 0; u < 2; u++) {
                    int idx = t + u * 256, row = idx >> 2, ch = (idx & 3) << 3;
                    size_t go = (size_t)(nn * 128 + row) * 256 + nk * 32 + ch;
                    rwh[u] = *(const uint4*)(W1hi + go);
                    rwl[u] = *(const uint4*)(W1lo + go);
                }
            }
#pragma unroll
            for (int ks = 0; ks < 2; ks++) {
                int kpos = k0 * 32 + ks * 16;
                uint32_t bh[4][2], blo_[4][2];
#pragma unroll
                for (int ntp = 0; ntp < 2; ntp++) {
                    unsigned wo = (wn * 32 + ntp * 16 + b_nrow) * 40 + ks * 16 + b_kc;
                    ldsm_x4_b2(bh[2 * ntp],   bh[2 * ntp + 1],
                               wB + 2u * ((buf * 2 + 0) * 5120 + wo));
                    ldsm_x4_b2(blo_[2 * ntp], blo_[2 * ntp + 1],
                               wB + 2u * ((buf * 2 + 1) * 5120 + wo));
                }
#pragma unroll
                for (int mt = 0; mt < 4; mt++) {
                    unsigned ao = (wm * 64 + mt * 16 + a_mrow) * 264 + kpos + a_kc;
                    uint32_t af[4];
                    ldsm_x4(af, aPhiB + 2u * ao);
#pragma unroll
                    for (int nt = 0; nt < 4; nt++) mma16816(acc[mt][nt], af, bh[nt]);
#pragma unroll
                    for (int nt = 0; nt < 4; nt++) mma16816(acc[mt][nt], af, blo_[nt]);
                    ldsm_x4(af, aPloB + 2u * ao);
#pragma unroll
                    for (int nt = 0; nt < 4; nt++) mma16816(acc[mt][nt], af, bh[nt]);
                }
            }
            buf ^= 1;
        }
        // fold this n-chunk into rowsums
#pragma unroll
        for (int mt = 0; mt < 4; mt++)
#pragma unroll
            for (int nt = 0; nt < 4; nt++) {
                int col = n0 + wn * 32 + nt * 8 + ((lane & 3) << 1);
                float2 bz = *(const float2*)(b1 + col);
                float2 wz = *(const float2*)(w2 + col);
                float* c = acc[mt][nt];
                rowsum[mt][0] += siluf(c[0] + bz.x) * wz.x + siluf(c[1] + bz.y) * wz.y;
                rowsum[mt][1] += siluf(c[2] + bz.x) * wz.x + siluf(c[3] + bz.y) * wz.y;
            }
    }

    // reduce over the 4 lanes sharing a row, then across the 4 n-warps
#pragma unroll
    for (int mt = 0; mt < 4; mt++)
#pragma unroll
        for (int p = 0; p < 2; p++) {
            float v = rowsum[mt][p];
            v += __shfl_xor_sync(0xffffffffu, v, 1);
            v += __shfl_xor_sync(0xffffffffu, v, 2);
            rowsum[mt][p] = v;
        }
    __syncthreads();
    if ((lane & 3) == 0) {
#pragma unroll
        for (int mt = 0; mt < 4; mt++)
#pragma unroll
            for (int p = 0; p < 2; p++) {
                int r = wm * 64 + mt * 16 + (lane >> 2) + p * 8;
                redS[wn * 128 + r] = rowsum[mt][p];
            }
    }
    __syncthreads();
    if (t < 128) {
        float v = redS[t] + redS[128 + t] + redS[256 + t] + redS[384 + t];
        int r = m0 + t, b = r / NPAIR_U, p = r - b * NPAIR_U;
        O2[b * NPAIR + c_sA[p]] = v;   // (i,j)
        O2[b * NPAIR + c_sB[p]] = v;   // (j,i) — identical by symmetry
    }
}

// ---------------------------------------------------------------------------
// Final: score[p] = <wh[b,i1], h[b,i2]>, softmax per group-of-4, weighted sum.
// ---------------------------------------------------------------------------
__global__ __launch_bounds__(128)
void final_k(const __nv_bfloat16* __restrict__ Hhi, const __nv_bfloat16* __restrict__ Hlo,
             const float* __restrict__ WH, const float* __restrict__ O2,
             const float* __restrict__ mlp_b2, float* __restrict__ out)
{
    __shared__ float scoreS[4][NPAIR];
    const int wi = threadIdx.x >> 5, lane = threadIdx.x & 31;
    const int b = blockIdx.x * 4 + wi;
    const __nv_bfloat16* hbh = Hhi + (size_t)b * TEAMN * 256;
    const __nv_bfloat16* hbl = Hlo + (size_t)b * TEAMN * 256;
    const float* whb = WH + (size_t)b * TEAMN * 256;

    for (int p = 0; p < NPAIR; p++) {
        const float* wa = whb + c_i1[p] * 256;
        int ho = c_i2[p] * 256 + lane * 8;
        uint4 uh = *(const uint4*)(hbh + ho);
        uint4 ul = *(const uint4*)(hbl + ho);
        const __nv_bfloat162* ph = (const __nv_bfloat162*)&uh;
        const __nv_bfloat162* pl = (const __nv_bfloat162*)&ul;
        float xv[8];
        *(float4*)&xv[0] = *(const float4*)(wa + lane * 8);
        *(float4*)&xv[4] = *(const float4*)(wa + lane * 8 + 4);
        float s = 0.f;
#pragma unroll
        for (int j = 0; j < 4; j++) {
            float2 hh = __bfloat1622float2(ph[j]);
            float2 hl = __bfloat1622float2(pl[j]);
            s += xv[2 * j] * (hh.x + hl.x) + xv[2 * j + 1] * (hh.y + hl.y);
        }
#pragma unroll
        for (int off = 16; off > 0; off >>= 1)
            s += __shfl_down_sync(0xffffffffu, s, off);
        if (lane == 0) scoreS[wi][p] = s;
    }
    __syncwarp();

    float partial = 0.f;
    if (lane < TEAMN) {
        float sc[4];
#pragma unroll
        for (int j = 0; j < 4; j++) sc[j] = scoreS[wi][lane * 4 + j];
        float mx = fmaxf(fmaxf(sc[0], sc[1]), fmaxf(sc[2], sc[3]));
        float e[4], se = 0.f;
#pragma unroll
        for (int j = 0; j < 4; j++) { e[j] = __expf(sc[j] - mx); se += e[j]; }
        float bias2 = mlp_b2[0];
        float acc = 0.f;
#pragma unroll
        for (int j = 0; j < 4; j++)
            acc += e[j] * (O2[b * NPAIR + lane * 4 + j] + bias2);
        partial = acc / se;
    }
#pragma unroll
    for (int off = 16; off > 0; off >>= 1)
        partial += __shfl_down_sync(0xffffffffu, partial, off);
    if (lane == 0) out[b] = partial;
}

// ---------------------------------------------------------------------------
extern "C" void kernel_launch(void* const* d_in, const int* in_sizes, int n_in,
                              void* d_out, int out_size)
{
    const int*   team_ids = (const int*)  d_in[0];
    const float* emb      = (const float*)d_in[1];
    const float* fm_w1    = (const float*)d_in[2];
    const float* fm_b1    = (const float*)d_in[3];
    const float* fm_w2    = (const float*)d_in[4];
    const float* fm_b2    = (const float*)d_in[5];
    const float* att_w    = (const float*)d_in[6];
    const float* att_b    = (const float*)d_in[7];
    const float* mlp_w1   = (const float*)d_in[8];
    const float* mlp_b1   = (const float*)d_in[9];
    const float* mlp_w2   = (const float*)d_in[10];
    const float* mlp_b2   = (const float*)d_in[11];
    float* out = (float*)d_out;

    void *p_h1hi, *p_h1lo, *p_hhi, *p_hlo, *p_wh, *p_o2;
    void *p_w1hi, *p_w1lo, *p_w2hi, *p_w2lo, *p_awhi, *p_awlo, *p_m1hi, *p_m1lo;
    cudaGetSymbolAddress(&p_h1hi, g_h1hi); cudaGetSymbolAddress(&p_h1lo, g_h1lo);
    cudaGetSymbolAddress(&p_hhi,  g_hhi);  cudaGetSymbolAddress(&p_hlo,  g_hlo);
    cudaGetSymbolAddress(&p_wh,   g_wh);   cudaGetSymbolAddress(&p_o2,   g_o2);
    cudaGetSymbolAddress(&p_w1hi, g_w1hi); cudaGetSymbolAddress(&p_w1lo, g_w1lo);
    cudaGetSymbolAddress(&p_w2hi, g_w2hi); cudaGetSymbolAddress(&p_w2lo, g_w2lo);
    cudaGetSymbolAddress(&p_awhi, g_awhi); cudaGetSymbolAddress(&p_awlo, g_awlo);
    cudaGetSymbolAddress(&p_m1hi, g_m1hi); cudaGetSymbolAddress(&p_m1lo, g_m1lo);

    // split ALL weights in one launch (emb is split in-register inside fm1)
    splitw_k<<<(WTOT + 255) / 256, 256>>>(
        fm_w1, fm_w2, att_w, mlp_w1,
        (__nv_bfloat16*)p_w1hi, (__nv_bfloat16*)p_w1lo,
        (__nv_bfloat16*)p_w2hi, (__nv_bfloat16*)p_w2lo,
        (__nv_bfloat16*)p_awhi, (__nv_bfloat16*)p_awlo,
        (__nv_bfloat16*)p_m1hi, (__nv_bfloat16*)p_m1lo);

    // fm1: gather fp32 emb + in-register split + silu(x @ fm_w1^T + b1) -> h1 (hi/lo)
    mma_gemm_k<256, 0, true><<<dim3(4, NROW / 128), 256>>>(
        emb, nullptr, nullptr,
        (const __nv_bfloat16*)p_w1hi, (const __nv_bfloat16*)p_w1lo,
        fm_b1, (__nv_bfloat16*)p_h1hi, (__nv_bfloat16*)p_h1lo, nullptr, team_ids, 512);
    // fm2: h1 @ fm_w2^T + b2 -> h (hi/lo)
    mma_gemm_k<512, 1, false><<<dim3(2, NROW / 128), 256>>>(
        nullptr, (const __nv_bfloat16*)p_h1hi, (const __nv_bfloat16*)p_h1lo,
        (const __nv_bfloat16*)p_w2hi, (const __nv_bfloat16*)p_w2lo,
        fm_b2, (__nv_bfloat16*)p_hhi, (__nv_bfloat16*)p_hlo, nullptr, nullptr, 256);
    // att (hoisted per member): h @ att_w^T + att_b -> wh (fp32)
    mma_gemm_k<256, 2, false><<<dim3(2, NROW / 128), 256>>>(
        nullptr, (const __nv_bfloat16*)p_hhi, (const __nv_bfloat16*)p_hlo,
        (const __nv_bfloat16*)p_awhi, (const __nv_bfloat16*)p_awlo,
        att_b, nullptr, nullptr, (float*)p_wh, nullptr, 256);
    // pair MLP over unique pairs + order2 scatter -> o2
    cudaFuncSetAttribute(pairs_mma_k, cudaFuncAttributeMaxDynamicSharedMemorySize, PAIRS_SMEM);
    pairs_mma_k<<<MROW_U / 128, 256, PAIRS_SMEM>>>(
        (const __nv_bfloat16*)p_hhi, (const __nv_bfloat16*)p_hlo,
        (const __nv_bfloat16*)p_m1hi, (const __nv_bfloat16*)p_m1lo,
        mlp_b1, mlp_w2, (float*)p_o2);
    // scores + softmax + weighted sum
    final_k<<<BSZ / 4, 128>>>(
        (const __nv_bfloat16*)p_hhi, (const __nv_bfloat16*)p_hlo,
        (const float*)p_wh, (const float*)p_o2, mlp_b2, out);
}

// round 10
// speedup vs baseline: 3.7568x; 1.1469x over previous
#include <cuda_runtime.h>
#include <cuda_bf16.h>
#include <cstdint>

#define TEAMN   5
#define BSZ     16384
#define NROW    (BSZ * TEAMN)     // 81920 member rows
#define NPAIR   20
#define NPAIR_U 10                // unique unordered pairs (prod is symmetric)
#define MROW_U  (BSZ * NPAIR_U)   // 163840 unique pair rows
#define NPLAYER 131072
#define PD      256

// ---------------- scratch (static device globals; no runtime allocation) ----
__device__ __nv_bfloat16 g_h1hi[(size_t)NROW * 512];
__device__ __nv_bfloat16 g_h1lo[(size_t)NROW * 512];
__device__ __nv_bfloat16 g_hhi [(size_t)NROW * 256];
__device__ __nv_bfloat16 g_hlo [(size_t)NROW * 256];
__device__ float         g_wh  [(size_t)NROW * 256];
__device__ float         g_o2  [(size_t)BSZ * NPAIR];
__device__ __nv_bfloat16 g_w1hi[512 * 256], g_w1lo[512 * 256];
__device__ __nv_bfloat16 g_w2hi[256 * 512], g_w2lo[256 * 512];
__device__ __nv_bfloat16 g_awhi[256 * 256], g_awlo[256 * 256];
__device__ __nv_bfloat16 g_m1hi[512 * 256], g_m1lo[512 * 256];

__constant__ int c_i1[NPAIR] = {0,0,0,0, 1,1,1,1, 2,2,2,2, 3,3,3,3, 4,4,4,4};
__constant__ int c_i2[NPAIR] = {1,2,3,4, 0,2,3,4, 0,1,3,4, 0,1,2,4, 0,1,2,3};
__constant__ int c_u1[NPAIR_U] = {0,0,0,0, 1,1,1, 2,2, 3};
__constant__ int c_u2[NPAIR_U] = {1,2,3,4, 2,3,4, 3,4, 4};
__constant__ int c_sA[NPAIR_U] = {0,1,2,3, 5,6,7, 10,11, 15};
__constant__ int c_sB[NPAIR_U] = {4,8,12,16, 9,13,17, 14,18, 19};

__device__ __forceinline__ float siluf(float x) { return x / (1.0f + __expf(-x)); }

__device__ __forceinline__ unsigned smem_u32(const void* p) {
    return (unsigned)__cvta_generic_to_shared(p);
}
__device__ __forceinline__ void ldsm_x4(uint32_t* r, unsigned addr) {
    asm volatile("ldmatrix.sync.aligned.m8n8.x4.shared.b16 {%0,%1,%2,%3}, [%4];"
                 : "=r"(r[0]), "=r"(r[1]), "=r"(r[2]), "=r"(r[3]) : "r"(addr));
}
// one x4 delivering B fragments for TWO adjacent n-tiles (k16 each)
__device__ __forceinline__ void ldsm_x4_b2(uint32_t* b0, uint32_t* b1, unsigned addr) {
    asm volatile("ldmatrix.sync.aligned.m8n8.x4.shared.b16 {%0,%1,%2,%3}, [%4];"
                 : "=r"(b0[0]), "=r"(b0[1]), "=r"(b1[0]), "=r"(b1[1]) : "r"(addr));
}
__device__ __forceinline__ void mma16816(float* c, const uint32_t* a, const uint32_t* b) {
    asm volatile(
        "mma.sync.aligned.m16n8k16.row.col.f32.bf16.bf16.f32 "
        "{%0,%1,%2,%3}, {%4,%5,%6,%7}, {%8,%9}, {%0,%1,%2,%3};"
        : "+f"(c[0]), "+f"(c[1]), "+f"(c[2]), "+f"(c[3])
        : "r"(a[0]), "r"(a[1]), "r"(a[2]), "r"(a[3]), "r"(b[0]), "r"(b[1]));
}
__device__ __forceinline__ void cp16(unsigned saddr, const void* g) {
    asm volatile("cp.async.cg.shared.global [%0], [%1], 16;" :: "r"(saddr), "l"(g));
}
#define CP_COMMIT() asm volatile("cp.async.commit_group;" ::: "memory")
#define CP_WAIT1()  asm volatile("cp.async.wait_group 1;" ::: "memory")
#define CP_WAIT0()  asm volatile("cp.async.wait_group 0;" ::: "memory")

__device__ __forceinline__ void store_split2(__nv_bfloat16* hi, __nv_bfloat16* lo,
                                             size_t off, float y0, float y1) {
    __nv_bfloat16 h0 = __float2bfloat16(y0), h1 = __float2bfloat16(y1);
    *(__nv_bfloat162*)(hi + off) = __halves2bfloat162(h0, h1);
    *(__nv_bfloat162*)(lo + off) = __halves2bfloat162(
        __float2bfloat16(y0 - __bfloat162float(h0)),
        __float2bfloat16(y1 - __bfloat162float(h1)));
}

// ---------------------------------------------------------------------------
// Combined weight split: fm_w1, fm_w2, att_w, mlp_w1 -> (hi, lo) bf16 pairs
// ---------------------------------------------------------------------------
#define W1_N 131072
#define W2_N 131072
#define AW_N 65536
#define M1_N 131072
#define WTOT (W1_N + W2_N + AW_N + M1_N)

__global__ void splitw_k(const float* __restrict__ w1, const float* __restrict__ w2,
                         const float* __restrict__ aw, const float* __restrict__ m1,
                         __nv_bfloat16* __restrict__ w1h, __nv_bfloat16* __restrict__ w1l,
                         __nv_bfloat16* __restrict__ w2h, __nv_bfloat16* __restrict__ w2l,
                         __nv_bfloat16* __restrict__ awh, __nv_bfloat16* __restrict__ awl,
                         __nv_bfloat16* __restrict__ m1h, __nv_bfloat16* __restrict__ m1l)
{
    int i = blockIdx.x * 256 + threadIdx.x;
    if (i >= WTOT) return;
    const float* s; __nv_bfloat16 *hi, *lo; int j = i;
    if (j < W1_N)                { s = w1; hi = w1h; lo = w1l; }
    else if ((j -= W1_N) < W2_N) { s = w2; hi = w2h; lo = w2l; }
    else if ((j -= W2_N) < AW_N) { s = aw; hi = awh; lo = awl; }
    else { j -= AW_N;              s = m1; hi = m1h; lo = m1l; }
    float v = s[j];
    __nv_bfloat16 h = __float2bfloat16(v);
    hi[j] = h;
    lo[j] = __float2bfloat16(v - __bfloat162float(h));
}

// ---------------------------------------------------------------------------
// MERGED split-bf16 GEMM:  C[M,N] = ep(A[M,K] @ W[N,K]^T + bias)
// One pass over K: per 32-K chunk load Ahi,Alo,Whi,Wlo tiles ONCE (cp.async
// for W and non-gather A), then issue all 3 split terms from shared
// fragments: (Ahi·Whi) + (Alo·Whi) + (Ahi·Wlo). 24 ldsm / 96 mma per chunk
// vs 36/96 in the segmented form; 3x fewer STS+LDG; 2 syncs/chunk vs 3.
// GATHER: A = fp32 emb rows via ids, hi+lo split in registers (loaded once).
// EP: 0 = silu + split-store   1 = split-store   2 = fp32 store
// ---------------------------------------------------------------------------
// dyn smem: 2 buffers x 4 tiles x [128][40] bf16 = 81920 B
#define GEMM_SMEM 81920
#define TILE_H    5120            // halves per tile (128*40)

template <int K, int EP, bool GATHER>
__global__ __launch_bounds__(256, 2)
void mma_gemm_k(const float* __restrict__ Af,
                const __nv_bfloat16* __restrict__ Ahi, const __nv_bfloat16* __restrict__ Alo,
                const __nv_bfloat16* __restrict__ Whi, const __nv_bfloat16* __restrict__ Wlo,
                const float* __restrict__ bias,
                __nv_bfloat16* __restrict__ Chi, __nv_bfloat16* __restrict__ Clo,
                float* __restrict__ Cf, const int* __restrict__ ids, int N)
{
    constexpr int NC = K / 32;
    extern __shared__ __align__(16) __nv_bfloat16 smdyn[];
    __shared__ int idS[128];

    const int t = threadIdx.x;
    const int lane = t & 31, warp = t >> 5;
    const int wm = warp >> 2, wn = warp & 3;
    const int m0 = blockIdx.y * 128, n0 = blockIdx.x * 128;

    if constexpr (GATHER) {
        if (t < 128) idS[t] = ids[m0 + t];
        __syncthreads();
    }

    // per-thread tile-fill coords (2 rows of 8 halves each)
    const int r0 = t >> 2,          c0 = (t & 3) << 3;
    const int r1 = (t + 256) >> 2,  c1 = (t & 3) << 3;   // (t+256)&3 == t&3
    const unsigned smB = smem_u32(smdyn);

    float acc[4][4][4];
#pragma unroll
    for (int a = 0; a < 4; a++)
#pragma unroll
        for (int b = 0; b < 4; b++)
#pragma unroll
            for (int c = 0; c < 4; c++) acc[a][b][c] = 0.f;

    const int a_mrow = ((lane >> 3) & 1) * 8 + (lane & 7);
    const int a_kc   = (lane >> 4) * 8;
    const int b_nrow = ((lane >> 4) & 1) * 8 + (lane & 7);
    const int b_kc   = ((lane >> 3) & 1) * 8;

    auto issueW = [&](int c, int buf) {
        const int koff = c * 32;
        const unsigned bW = smB + (unsigned)(buf * 4 * TILE_H + 2 * TILE_H) * 2;
        cp16(bW + (unsigned)(r0 * 40 + c0) * 2,          Whi + (size_t)(n0 + r0) * K + koff + c0);
        cp16(bW + (unsigned)(r1 * 40 + c1) * 2,          Whi + (size_t)(n0 + r1) * K + koff + c1);
        cp16(bW + (unsigned)(TILE_H + r0 * 40 + c0) * 2, Wlo + (size_t)(n0 + r0) * K + koff + c0);
        cp16(bW + (unsigned)(TILE_H + r1 * 40 + c1) * 2, Wlo + (size_t)(n0 + r1) * K + koff + c1);
    };
    auto issueA = [&](int c, int buf) {      // non-gather only
        const int koff = c * 32;
        const unsigned bA = smB + (unsigned)(buf * 4 * TILE_H) * 2;
        cp16(bA + (unsigned)(r0 * 40 + c0) * 2,          Ahi + (size_t)(m0 + r0) * K + koff + c0);
        cp16(bA + (unsigned)(r1 * 40 + c1) * 2,          Ahi + (size_t)(m0 + r1) * K + koff + c1);
        cp16(bA + (unsigned)(TILE_H + r0 * 40 + c0) * 2, Alo + (size_t)(m0 + r0) * K + koff + c0);
        cp16(bA + (unsigned)(TILE_H + r1 * 40 + c1) * 2, Alo + (size_t)(m0 + r1) * K + koff + c1);
    };

    float4 rf[4];
    auto ldgA = [&](int c) {                 // gather only
        const int koff = c * 32;
        const float* s0 = Af + (size_t)idS[r0] * K + koff + c0;
        rf[0] = *(const float4*)s0; rf[1] = *(const float4*)(s0 + 4);
        const float* s1 = Af + (size_t)idS[r1] * K + koff + c1;
        rf[2] = *(const float4*)s1; rf[3] = *(const float4*)(s1 + 4);
    };
    auto stsA = [&](int buf) {               // gather only: split + store hi/lo
        __nv_bfloat16* base = smdyn + buf * 4 * TILE_H;
#pragma unroll
        for (int u = 0; u < 2; u++) {
            const float* f = (const float*)&rf[2 * u];
            const int ro = (u == 0) ? r0 : r1;
            const int ch = (u == 0) ? c0 : c1;
            __nv_bfloat16 vh[8], vl[8];
#pragma unroll
            for (int j = 0; j < 8; j++) {
                __nv_bfloat16 h = __float2bfloat16(f[j]);
                vh[j] = h;
                vl[j] = __float2bfloat16(f[j] - __bfloat162float(h));
            }
            *(uint4*)(base + ro * 40 + ch)          = *(uint4*)vh;
            *(uint4*)(base + TILE_H + ro * 40 + ch) = *(uint4*)vl;
        }
    };

    // prologue: chunk 0
    if constexpr (!GATHER) issueA(0, 0);
    issueW(0, 0);
    CP_COMMIT();
    if constexpr (GATHER) ldgA(0);

    for (int c = 0; c < NC; c++) {
        const int buf = c & 1;
        if constexpr (GATHER) stsA(buf);
        if (c + 1 < NC) {
            const int nb = (c + 1) & 1;
            if constexpr (!GATHER) issueA(c + 1, nb);
            issueW(c + 1, nb);
            CP_COMMIT();
            if constexpr (GATHER) ldgA(c + 1);
            CP_WAIT1();
        } else {
            CP_WAIT0();
        }
        __syncthreads();

        const unsigned bB  = smB + (unsigned)(buf * 4 * TILE_H) * 2;
        const unsigned aHi = bB;
        const unsigned aLo = bB + TILE_H * 2;
        const unsigned wHi = bB + 2 * TILE_H * 2;
        const unsigned wLo = bB + 3 * TILE_H * 2;
#pragma unroll
        for (int ks = 0; ks < 2; ks++) {
            uint32_t bh[4][2], bl[4][2];
#pragma unroll
            for (int ntp = 0; ntp < 2; ntp++) {
                const unsigned wo = (unsigned)((wn * 32 + ntp * 16 + b_nrow) * 40 + ks * 16 + b_kc) * 2;
                ldsm_x4_b2(bh[2 * ntp], bh[2 * ntp + 1], wHi + wo);
                ldsm_x4_b2(bl[2 * ntp], bl[2 * ntp + 1], wLo + wo);
            }
#pragma unroll
            for (int mt = 0; mt < 4; mt++) {
                const unsigned ao = (unsigned)((wm * 64 + mt * 16 + a_mrow) * 40 + ks * 16 + a_kc) * 2;
                uint32_t afh[4], afl[4];
                ldsm_x4(afh, aHi + ao);
                ldsm_x4(afl, aLo + ao);
#pragma unroll
                for (int nt = 0; nt < 4; nt++) mma16816(acc[mt][nt], afh, bh[nt]);
#pragma unroll
                for (int nt = 0; nt < 4; nt++) mma16816(acc[mt][nt], afl, bh[nt]);
#pragma unroll
                for (int nt = 0; nt < 4; nt++) mma16816(acc[mt][nt], afh, bl[nt]);
            }
        }
        __syncthreads();   // all warps done reading before this buffer is refilled
    }

    // epilogue
#pragma unroll
    for (int mt = 0; mt < 4; mt++)
#pragma unroll
        for (int nt = 0; nt < 4; nt++) {
            int row = m0 + wm * 64 + mt * 16 + (lane >> 2);
            int col = n0 + wn * 32 + nt * 8 + ((lane & 3) << 1);
            float2 bz = *(const float2*)(bias + col);
            float* c = acc[mt][nt];
            float y0 = c[0] + bz.x, y1 = c[1] + bz.y;
            float y2 = c[2] + bz.x, y3 = c[3] + bz.y;
            if (EP == 0) { y0 = siluf(y0); y1 = siluf(y1); y2 = siluf(y2); y3 = siluf(y3); }
            if (EP <= 1) {
                store_split2(Chi, Clo, (size_t)row * N + col, y0, y1);
                store_split2(Chi, Clo, (size_t)(row + 8) * N + col, y2, y3);
            } else {
                *(float2*)(Cf + (size_t)row * N + col)       = make_float2(y0, y1);
                *(float2*)(Cf + (size_t)(row + 8) * N + col) = make_float2(y2, y3);
            }
        }
}

// ---------------------------------------------------------------------------
// Pair-MLP kernel over UNIQUE pairs (unchanged from R9 — proven).
// ---------------------------------------------------------------------------
#define PAIRS_SMEM (2 * 128 * 264 * 2 + 2 * 2 * 128 * 40 * 2 + 256 * 4 + 512 * 4)

__global__ __launch_bounds__(256)
void pairs_mma_k(const __nv_bfloat16* __restrict__ Hhi, const __nv_bfloat16* __restrict__ Hlo,
                 const __nv_bfloat16* __restrict__ W1hi, const __nv_bfloat16* __restrict__ W1lo,
                 const float* __restrict__ b1, const float* __restrict__ w2,
                 float* __restrict__ O2)
{
    extern __shared__ __align__(16) char smraw[];
    __nv_bfloat16* Aphi = (__nv_bfloat16*)smraw;            // [128][264]
    __nv_bfloat16* Aplo = Aphi + 128 * 264;                 // [128][264]
    __nv_bfloat16* Wt   = Aplo + 128 * 264;                 // [2 buf][2 hl][128][40]
    int*   off1s = (int*)(Wt + 2 * 2 * 128 * 40);
    int*   off2s = off1s + 128;
    float* redS  = (float*)(off2s + 128);                   // [4][128]

    const int t = threadIdx.x, lane = t & 31, warp = t >> 5;
    const int wm = warp >> 2, wn = warp & 3;
    const int m0 = blockIdx.x * 128;

    if (t < 128) {
        int r = m0 + t, b = r / NPAIR_U, p = r - b * NPAIR_U;
        off1s[t] = (b * TEAMN + c_u1[p]) * 256;
        off2s[t] = (b * TEAMN + c_u2[p]) * 256;
    }
    __syncthreads();

    // ---- phase 1: build product tiles (hi/lo) ----
    {
        int cidx = t;
#pragma unroll 4
        for (int i = 0; i < 16; i++, cidx += 256) {
            int row = cidx >> 5;
            int ch  = (cidx & 31) << 3;
            int o1 = off1s[row] + ch, o2 = off2s[row] + ch;
            uint4 u1h = *(const uint4*)(Hhi + o1);
            uint4 u1l = *(const uint4*)(Hlo + o1);
            uint4 u2h = *(const uint4*)(Hhi + o2);
            uint4 u2l = *(const uint4*)(Hlo + o2);
            const __nv_bfloat162* p1h = (const __nv_bfloat162*)&u1h;
            const __nv_bfloat162* p1l = (const __nv_bfloat162*)&u1l;
            const __nv_bfloat162* p2h = (const __nv_bfloat162*)&u2h;
            const __nv_bfloat162* p2l = (const __nv_bfloat162*)&u2l;
            __nv_bfloat162 oph[4], opl[4];
#pragma unroll
            for (int j = 0; j < 4; j++) {
                float2 a   = __bfloat1622float2(p1h[j]);
                float2 al  = __bfloat1622float2(p1l[j]);
                float2 b_  = __bfloat1622float2(p2h[j]);
                float2 bl_ = __bfloat1622float2(p2l[j]);
                float f0 = (a.x + al.x) * (b_.x + bl_.x);
                float f1 = (a.y + al.y) * (b_.y + bl_.y);
                __nv_bfloat16 h0 = __float2bfloat16(f0), h1 = __float2bfloat16(f1);
                oph[j] = __halves2bfloat162(h0, h1);
                opl[j] = __halves2bfloat162(
                    __float2bfloat16(f0 - __bfloat162float(h0)),
                    __float2bfloat16(f1 - __bfloat162float(h1)));
            }
            *(uint4*)(Aphi + row * 264 + ch) = *(uint4*)oph;
            *(uint4*)(Aplo + row * 264 + ch) = *(uint4*)opl;
        }
    }

    float rowsum[4][2];
#pragma unroll
    for (int a = 0; a < 4; a++) { rowsum[a][0] = 0.f; rowsum[a][1] = 0.f; }

    const int a_mrow = ((lane >> 3) & 1) * 8 + (lane & 7);
    const int a_kc   = (lane >> 4) * 8;
    const int b_nrow = ((lane >> 4) & 1) * 8 + (lane & 7);
    const int b_kc   = ((lane >> 3) & 1) * 8;
    const unsigned aPhiB = smem_u32(Aphi);
    const unsigned aPloB = smem_u32(Aplo);
    const unsigned wB    = smem_u32(Wt);

    uint4 rwh[2], rwl[2];
#pragma unroll
    for (int u = 0; u < 2; u++) {    // prefetch n0=0, k0=0
        int idx = t + u * 256, row = idx >> 2, ch = (idx & 3) << 3;
        size_t go = (size_t)row * 256 + ch;
        rwh[u] = *(const uint4*)(W1hi + go);
        rwl[u] = *(const uint4*)(W1lo + go);
    }

    int buf = 0;
    for (int n0i = 0; n0i < 4; n0i++) {
        int n0 = n0i * 128;
        float acc[4][4][4];
#pragma unroll
        for (int a = 0; a < 4; a++)
#pragma unroll
            for (int b = 0; b < 4; b++)
#pragma unroll
                for (int c = 0; c < 4; c++) acc[a][b][c] = 0.f;

        for (int k0 = 0; k0 < 8; k0++) {
#pragma unroll
            for (int u = 0; u < 2; u++) {
                int idx = t + u * 256, row = idx >> 2, ch = (idx & 3) << 3;
                *(uint4*)(Wt + (buf * 2 + 0) * 5120 + row * 40 + ch) = rwh[u];
                *(uint4*)(Wt + (buf * 2 + 1) * 5120 + row * 40 + ch) = rwl[u];
            }
            __syncthreads();
            if (!(n0i == 3 && k0 == 7)) {
                int nk = k0 + 1, nn = n0i;
                if (nk == 8) { nk = 0; nn++; }
#pragma unroll
                for (int u = 0; u < 2; u++) {
                    int idx = t + u * 256, row = idx >> 2, ch = (idx & 3) << 3;
                    size_t go = (size_t)(nn * 128 + row) * 256 + nk * 32 + ch;
                    rwh[u] = *(const uint4*)(W1hi + go);
                    rwl[u] = *(const uint4*)(W1lo + go);
                }
            }
#pragma unroll
            for (int ks = 0; ks < 2; ks++) {
                int kpos = k0 * 32 + ks * 16;
                uint32_t bh[4][2], blo_[4][2];
#pragma unroll
                for (int ntp = 0; ntp < 2; ntp++) {
                    unsigned wo = (wn * 32 + ntp * 16 + b_nrow) * 40 + ks * 16 + b_kc;
                    ldsm_x4_b2(bh[2 * ntp],   bh[2 * ntp + 1],
                               wB + 2u * ((buf * 2 + 0) * 5120 + wo));
                    ldsm_x4_b2(blo_[2 * ntp], blo_[2 * ntp + 1],
                               wB + 2u * ((buf * 2 + 1) * 5120 + wo));
                }
#pragma unroll
                for (int mt = 0; mt < 4; mt++) {
                    unsigned ao = (wm * 64 + mt * 16 + a_mrow) * 264 + kpos + a_kc;
                    uint32_t af[4];
                    ldsm_x4(af, aPhiB + 2u * ao);
#pragma unroll
                    for (int nt = 0; nt < 4; nt++) mma16816(acc[mt][nt], af, bh[nt]);
#pragma unroll
                    for (int nt = 0; nt < 4; nt++) mma16816(acc[mt][nt], af, blo_[nt]);
                    ldsm_x4(af, aPloB + 2u * ao);
#pragma unroll
                    for (int nt = 0; nt < 4; nt++) mma16816(acc[mt][nt], af, bh[nt]);
                }
            }
            buf ^= 1;
        }
        // fold this n-chunk into rowsums
#pragma unroll
        for (int mt = 0; mt < 4; mt++)
#pragma unroll
            for (int nt = 0; nt < 4; nt++) {
                int col = n0 + wn * 32 + nt * 8 + ((lane & 3) << 1);
                float2 bz = *(const float2*)(b1 + col);
                float2 wz = *(const float2*)(w2 + col);
                float* c = acc[mt][nt];
                rowsum[mt][0] += siluf(c[0] + bz.x) * wz.x + siluf(c[1] + bz.y) * wz.y;
                rowsum[mt][1] += siluf(c[2] + bz.x) * wz.x + siluf(c[3] + bz.y) * wz.y;
            }
    }

    // reduce over the 4 lanes sharing a row, then across the 4 n-warps
#pragma unroll
    for (int mt = 0; mt < 4; mt++)
#pragma unroll
        for (int p = 0; p < 2; p++) {
            float v = rowsum[mt][p];
            v += __shfl_xor_sync(0xffffffffu, v, 1);
            v += __shfl_xor_sync(0xffffffffu, v, 2);
            rowsum[mt][p] = v;
        }
    __syncthreads();
    if ((lane & 3) == 0) {
#pragma unroll
        for (int mt = 0; mt < 4; mt++)
#pragma unroll
            for (int p = 0; p < 2; p++) {
                int r = wm * 64 + mt * 16 + (lane >> 2) + p * 8;
                redS[wn * 128 + r] = rowsum[mt][p];
            }
    }
    __syncthreads();
    if (t < 128) {
        float v = redS[t] + redS[128 + t] + redS[256 + t] + redS[384 + t];
        int r = m0 + t, b = r / NPAIR_U, p = r - b * NPAIR_U;
        O2[b * NPAIR + c_sA[p]] = v;   // (i,j)
        O2[b * NPAIR + c_sB[p]] = v;   // (j,i) — identical by symmetry
    }
}

// ---------------------------------------------------------------------------
// Final: score[p] = <wh[b,i1], h[b,i2]>, softmax per group-of-4, weighted sum.
// ---------------------------------------------------------------------------
__global__ __launch_bounds__(128)
void final_k(const __nv_bfloat16* __restrict__ Hhi, const __nv_bfloat16* __restrict__ Hlo,
             const float* __restrict__ WH, const float* __restrict__ O2,
             const float* __restrict__ mlp_b2, float* __restrict__ out)
{
    __shared__ float scoreS[4][NPAIR];
    const int wi = threadIdx.x >> 5, lane = threadIdx.x & 31;
    const int b = blockIdx.x * 4 + wi;
    const __nv_bfloat16* hbh = Hhi + (size_t)b * TEAMN * 256;
    const __nv_bfloat16* hbl = Hlo + (size_t)b * TEAMN * 256;
    const float* whb = WH + (size_t)b * TEAMN * 256;

    for (int p = 0; p < NPAIR; p++) {
        const float* wa = whb + c_i1[p] * 256;
        int ho = c_i2[p] * 256 + lane * 8;
        uint4 uh = *(const uint4*)(hbh + ho);
        uint4 ul = *(const uint4*)(hbl + ho);
        const __nv_bfloat162* ph = (const __nv_bfloat162*)&uh;
        const __nv_bfloat162* pl = (const __nv_bfloat162*)&ul;
        float xv[8];
        *(float4*)&xv[0] = *(const float4*)(wa + lane * 8);
        *(float4*)&xv[4] = *(const float4*)(wa + lane * 8 + 4);
        float s = 0.f;
#pragma unroll
        for (int j = 0; j < 4; j++) {
            float2 hh = __bfloat1622float2(ph[j]);
            float2 hl = __bfloat1622float2(pl[j]);
            s += xv[2 * j] * (hh.x + hl.x) + xv[2 * j + 1] * (hh.y + hl.y);
        }
#pragma unroll
        for (int off = 16; off > 0; off >>= 1)
            s += __shfl_down_sync(0xffffffffu, s, off);
        if (lane == 0) scoreS[wi][p] = s;
    }
    __syncwarp();

    float partial = 0.f;
    if (lane < TEAMN) {
        float sc[4];
#pragma unroll
        for (int j = 0; j < 4; j++) sc[j] = scoreS[wi][lane * 4 + j];
        float mx = fmaxf(fmaxf(sc[0], sc[1]), fmaxf(sc[2], sc[3]));
        float e[4], se = 0.f;
#pragma unroll
        for (int j = 0; j < 4; j++) { e[j] = __expf(sc[j] - mx); se += e[j]; }
        float bias2 = mlp_b2[0];
        float acc = 0.f;
#pragma unroll
        for (int j = 0; j < 4; j++)
            acc += e[j] * (O2[b * NPAIR + lane * 4 + j] + bias2);
        partial = acc / se;
    }
#pragma unroll
    for (int off = 16; off > 0; off >>= 1)
        partial += __shfl_down_sync(0xffffffffu, partial, off);
    if (lane == 0) out[b] = partial;
}

// ---------------------------------------------------------------------------
extern "C" void kernel_launch(void* const* d_in, const int* in_sizes, int n_in,
                              void* d_out, int out_size)
{
    const int*   team_ids = (const int*)  d_in[0];
    const float* emb      = (const float*)d_in[1];
    const float* fm_w1    = (const float*)d_in[2];
    const float* fm_b1    = (const float*)d_in[3];
    const float* fm_w2    = (const float*)d_in[4];
    const float* fm_b2    = (const float*)d_in[5];
    const float* att_w    = (const float*)d_in[6];
    const float* att_b    = (const float*)d_in[7];
    const float* mlp_w1   = (const float*)d_in[8];
    const float* mlp_b1   = (const float*)d_in[9];
    const float* mlp_w2   = (const float*)d_in[10];
    const float* mlp_b2   = (const float*)d_in[11];
    float* out = (float*)d_out;

    void *p_h1hi, *p_h1lo, *p_hhi, *p_hlo, *p_wh, *p_o2;
    void *p_w1hi, *p_w1lo, *p_w2hi, *p_w2lo, *p_awhi, *p_awlo, *p_m1hi, *p_m1lo;
    cudaGetSymbolAddress(&p_h1hi, g_h1hi); cudaGetSymbolAddress(&p_h1lo, g_h1lo);
    cudaGetSymbolAddress(&p_hhi,  g_hhi);  cudaGetSymbolAddress(&p_hlo,  g_hlo);
    cudaGetSymbolAddress(&p_wh,   g_wh);   cudaGetSymbolAddress(&p_o2,   g_o2);
    cudaGetSymbolAddress(&p_w1hi, g_w1hi); cudaGetSymbolAddress(&p_w1lo, g_w1lo);
    cudaGetSymbolAddress(&p_w2hi, g_w2hi); cudaGetSymbolAddress(&p_w2lo, g_w2lo);
    cudaGetSymbolAddress(&p_awhi, g_awhi); cudaGetSymbolAddress(&p_awlo, g_awlo);
    cudaGetSymbolAddress(&p_m1hi, g_m1hi); cudaGetSymbolAddress(&p_m1lo, g_m1lo);

    cudaFuncSetAttribute(mma_gemm_k<256, 0, true>,
                         cudaFuncAttributeMaxDynamicSharedMemorySize, GEMM_SMEM);
    cudaFuncSetAttribute(mma_gemm_k<512, 1, false>,
                         cudaFuncAttributeMaxDynamicSharedMemorySize, GEMM_SMEM);
    cudaFuncSetAttribute(mma_gemm_k<256, 2, false>,
                         cudaFuncAttributeMaxDynamicSharedMemorySize, GEMM_SMEM);
    cudaFuncSetAttribute(pairs_mma_k,
                         cudaFuncAttributeMaxDynamicSharedMemorySize, PAIRS_SMEM);

    // split ALL weights in one launch (emb is split in-register inside fm1)
    splitw_k<<<(WTOT + 255) / 256, 256>>>(
        fm_w1, fm_w2, att_w, mlp_w1,
        (__nv_bfloat16*)p_w1hi, (__nv_bfloat16*)p_w1lo,
        (__nv_bfloat16*)p_w2hi, (__nv_bfloat16*)p_w2lo,
        (__nv_bfloat16*)p_awhi, (__nv_bfloat16*)p_awlo,
        (__nv_bfloat16*)p_m1hi, (__nv_bfloat16*)p_m1lo);

    // fm1: gather fp32 emb + in-register split + silu(x @ fm_w1^T + b1) -> h1 (hi/lo)
    mma_gemm_k<256, 0, true><<<dim3(4, NROW / 128), 256, GEMM_SMEM>>>(
        emb, nullptr, nullptr,
        (const __nv_bfloat16*)p_w1hi, (const __nv_bfloat16*)p_w1lo,
        fm_b1, (__nv_bfloat16*)p_h1hi, (__nv_bfloat16*)p_h1lo, nullptr, team_ids, 512);
    // fm2: h1 @ fm_w2^T + b2 -> h (hi/lo)
    mma_gemm_k<512, 1, false><<<dim3(2, NROW / 128), 256, GEMM_SMEM>>>(
        nullptr, (const __nv_bfloat16*)p_h1hi, (const __nv_bfloat16*)p_h1lo,
        (const __nv_bfloat16*)p_w2hi, (const __nv_bfloat16*)p_w2lo,
        fm_b2, (__nv_bfloat16*)p_hhi, (__nv_bfloat16*)p_hlo, nullptr, nullptr, 256);
    // att (hoisted per member): h @ att_w^T + att_b -> wh (fp32)
    mma_gemm_k<256, 2, false><<<dim3(2, NROW / 128), 256, GEMM_SMEM>>>(
        nullptr, (const __nv_bfloat16*)p_hhi, (const __nv_bfloat16*)p_hlo,
        (const __nv_bfloat16*)p_awhi, (const __nv_bfloat16*)p_awlo,
        att_b, nullptr, nullptr, (float*)p_wh, nullptr, 256);
    // pair MLP over unique pairs + order2 scatter -> o2
    pairs_mma_k<<<MROW_U / 128, 256, PAIRS_SMEM>>>(
        (const __nv_bfloat16*)p_hhi, (const __nv_bfloat16*)p_hlo,
        (const __nv_bfloat16*)p_m1hi, (const __nv_bfloat16*)p_m1lo,
        mlp_b1, mlp_w2, (float*)p_o2);
    // scores + softmax + weighted sum
    final_k<<<BSZ / 4, 128>>>(
        (const __nv_bfloat16*)p_hhi, (const __nv_bfloat16*)p_hlo,
        (const float*)p_wh, (const float*)p_o2, mlp_b2, out);
}

// round 11
// speedup vs baseline: 3.9539x; 1.0525x over previous
#include <cuda_runtime.h>
#include <cuda_bf16.h>
#include <cstdint>

#define TEAMN   5
#define BSZ     16384
#define NROW    (BSZ * TEAMN)     // 81920 member rows
#define NPAIR   20
#define NPAIR_U 10                // unique unordered pairs (prod is symmetric)
#define MROW_U  (BSZ * NPAIR_U)   // 163840 unique pair rows
#define NPLAYER 131072
#define PD      256

// ---------------- scratch (static device globals; no runtime allocation) ----
__device__ __nv_bfloat16 g_h1hi[(size_t)NROW * 512];
__device__ __nv_bfloat16 g_h1lo[(size_t)NROW * 512];
__device__ __nv_bfloat16 g_hhi [(size_t)NROW * 256];
__device__ __nv_bfloat16 g_hlo [(size_t)NROW * 256];
__device__ float         g_wh  [(size_t)NROW * 256];
__device__ float         g_o2  [(size_t)BSZ * NPAIR];
__device__ __nv_bfloat16 g_w1hi[512 * 256], g_w1lo[512 * 256];
__device__ __nv_bfloat16 g_w2hi[256 * 512], g_w2lo[256 * 512];
__device__ __nv_bfloat16 g_awhi[256 * 256], g_awlo[256 * 256];
__device__ __nv_bfloat16 g_m1hi[512 * 256], g_m1lo[512 * 256];

__constant__ int c_i1[NPAIR] = {0,0,0,0, 1,1,1,1, 2,2,2,2, 3,3,3,3, 4,4,4,4};
__constant__ int c_i2[NPAIR] = {1,2,3,4, 0,2,3,4, 0,1,3,4, 0,1,2,4, 0,1,2,3};
__constant__ int c_u1[NPAIR_U] = {0,0,0,0, 1,1,1, 2,2, 3};
__constant__ int c_u2[NPAIR_U] = {1,2,3,4, 2,3,4, 3,4, 4};
__constant__ int c_sA[NPAIR_U] = {0,1,2,3, 5,6,7, 10,11, 15};
__constant__ int c_sB[NPAIR_U] = {4,8,12,16, 9,13,17, 14,18, 19};

__device__ __forceinline__ float siluf(float x) { return x / (1.0f + __expf(-x)); }

__device__ __forceinline__ unsigned smem_u32(const void* p) {
    return (unsigned)__cvta_generic_to_shared(p);
}
__device__ __forceinline__ void ldsm_x4(uint32_t* r, unsigned addr) {
    asm volatile("ldmatrix.sync.aligned.m8n8.x4.shared.b16 {%0,%1,%2,%3}, [%4];"
                 : "=r"(r[0]), "=r"(r[1]), "=r"(r[2]), "=r"(r[3]) : "r"(addr));
}
// one x4 delivering B fragments for TWO adjacent n-tiles (k16 each)
__device__ __forceinline__ void ldsm_x4_b2(uint32_t* b0, uint32_t* b1, unsigned addr) {
    asm volatile("ldmatrix.sync.aligned.m8n8.x4.shared.b16 {%0,%1,%2,%3}, [%4];"
                 : "=r"(b0[0]), "=r"(b0[1]), "=r"(b1[0]), "=r"(b1[1]) : "r"(addr));
}
__device__ __forceinline__ void mma16816(float* c, const uint32_t* a, const uint32_t* b) {
    asm volatile(
        "mma.sync.aligned.m16n8k16.row.col.f32.bf16.bf16.f32 "
        "{%0,%1,%2,%3}, {%4,%5,%6,%7}, {%8,%9}, {%0,%1,%2,%3};"
        : "+f"(c[0]), "+f"(c[1]), "+f"(c[2]), "+f"(c[3])
        : "r"(a[0]), "r"(a[1]), "r"(a[2]), "r"(a[3]), "r"(b[0]), "r"(b[1]));
}
__device__ __forceinline__ void cp16(unsigned saddr, const void* g) {
    asm volatile("cp.async.cg.shared.global [%0], [%1], 16;" :: "r"(saddr), "l"(g));
}
#define CP_COMMIT() asm volatile("cp.async.commit_group;" ::: "memory")
#define CP_WAIT1()  asm volatile("cp.async.wait_group 1;" ::: "memory")
#define CP_WAIT0()  asm volatile("cp.async.wait_group 0;" ::: "memory")

__device__ __forceinline__ void store_split2(__nv_bfloat16* hi, __nv_bfloat16* lo,
                                             size_t off, float y0, float y1) {
    __nv_bfloat16 h0 = __float2bfloat16(y0), h1 = __float2bfloat16(y1);
    *(__nv_bfloat162*)(hi + off) = __halves2bfloat162(h0, h1);
    *(__nv_bfloat162*)(lo + off) = __halves2bfloat162(
        __float2bfloat16(y0 - __bfloat162float(h0)),
        __float2bfloat16(y1 - __bfloat162float(h1)));
}

// ---------------------------------------------------------------------------
// Combined weight split: fm_w1, fm_w2, att_w, mlp_w1 -> (hi, lo) bf16 pairs
// ---------------------------------------------------------------------------
#define W1_N 131072
#define W2_N 131072
#define AW_N 65536
#define M1_N 131072
#define WTOT (W1_N + W2_N + AW_N + M1_N)

__global__ void splitw_k(const float* __restrict__ w1, const float* __restrict__ w2,
                         const float* __restrict__ aw, const float* __restrict__ m1,
                         __nv_bfloat16* __restrict__ w1h, __nv_bfloat16* __restrict__ w1l,
                         __nv_bfloat16* __restrict__ w2h, __nv_bfloat16* __restrict__ w2l,
                         __nv_bfloat16* __restrict__ awh, __nv_bfloat16* __restrict__ awl,
                         __nv_bfloat16* __restrict__ m1h, __nv_bfloat16* __restrict__ m1l)
{
    int i = blockIdx.x * 256 + threadIdx.x;
    if (i >= WTOT) return;
    const float* s; __nv_bfloat16 *hi, *lo; int j = i;
    if (j < W1_N)                { s = w1; hi = w1h; lo = w1l; }
    else if ((j -= W1_N) < W2_N) { s = w2; hi = w2h; lo = w2l; }
    else if ((j -= W2_N) < AW_N) { s = aw; hi = awh; lo = awl; }
    else { j -= AW_N;              s = m1; hi = m1h; lo = m1l; }
    float v = s[j];
    __nv_bfloat16 h = __float2bfloat16(v);
    hi[j] = h;
    lo[j] = __float2bfloat16(v - __bfloat162float(h));
}

// ---------------------------------------------------------------------------
// MERGED split-bf16 GEMM, 3-stage cp.async pipeline, ONE sync per K-chunk.
// C[M,N] = ep(A[M,K] @ W[N,K]^T + bias); terms (Ahi·Whi)+(Alo·Whi)+(Ahi·Wlo).
// SMEM: 3 stages x 4 tiles x [128 rows x 64B], XOR swizzle
//   seg(row, c16) = c16 ^ ((row>>1)&3)  -> conflict-free STS + ldmatrix.
// Loop: wait_group(1); sync; issue(c+2) [safe: all warps past compute(c-1)];
//       compute(c).  GATHER: fp32 emb gathered, hi/lo split in registers,
//       stsA(c) before the sync (last reader of that region was compute(c-3)).
// EP: 0 = silu + split-store   1 = split-store   2 = fp32 store
// ---------------------------------------------------------------------------
#define GEMM_SMEM  98304          // 3 x 32768
#define STAGE_B    32768
#define TILE_B     8192           // 128 x 64 bytes

template <int K, int EP, bool GATHER>
__global__ __launch_bounds__(256, 2)
void mma_gemm_k(const float* __restrict__ Af,
                const __nv_bfloat16* __restrict__ Ahi, const __nv_bfloat16* __restrict__ Alo,
                const __nv_bfloat16* __restrict__ Whi, const __nv_bfloat16* __restrict__ Wlo,
                const float* __restrict__ bias,
                __nv_bfloat16* __restrict__ Chi, __nv_bfloat16* __restrict__ Clo,
                float* __restrict__ Cf, const int* __restrict__ ids, int N)
{
    constexpr int NC = K / 32;
    extern __shared__ __align__(16) __nv_bfloat16 smdyn[];
    __shared__ int idS[128];

    const int t = threadIdx.x;
    const int lane = t & 31, warp = t >> 5;
    const int wm = warp >> 2, wn = warp & 3;
    const int m0 = blockIdx.y * 128, n0 = blockIdx.x * 128;

    if constexpr (GATHER) {
        if (t < 128) idS[t] = ids[m0 + t];
        __syncthreads();
    }

    // fill coords: thread t handles 16B chunk cc of rows r0 and r0+64
    const int r0 = t >> 2, cc = t & 3;
    const int r1 = r0 + 64;
    const unsigned d0 = (unsigned)(r0 * 64 + ((cc ^ ((r0 >> 1) & 3)) << 4));
    const unsigned d1 = (unsigned)(r1 * 64 + ((cc ^ ((r1 >> 1) & 3)) << 4));
    const int srcoff = cc * 8;    // element offset within 32-wide chunk
    const unsigned smB = smem_u32(smdyn);

    float acc[4][4][4];
#pragma unroll
    for (int a = 0; a < 4; a++)
#pragma unroll
        for (int b = 0; b < 4; b++)
#pragma unroll
            for (int c = 0; c < 4; c++) acc[a][b][c] = 0.f;

    const int a_mrow = ((lane >> 3) & 1) * 8 + (lane & 7);
    const int a_c16  = lane >> 4;            // 0..1: k-half
    const int b_nrow = ((lane >> 4) & 1) * 8 + (lane & 7);
    const int b_c16  = (lane >> 3) & 1;      // 0..1: k-half

    auto issue = [&](int c) {
        const int koff = c * 32 + srcoff;
        const unsigned sb = smB + (unsigned)((c % 3) * STAGE_B);
        if constexpr (!GATHER) {
            cp16(sb + d0,              Ahi + (size_t)(m0 + r0) * K + koff);
            cp16(sb + d1,              Ahi + (size_t)(m0 + r1) * K + koff);
            cp16(sb + TILE_B + d0,     Alo + (size_t)(m0 + r0) * K + koff);
            cp16(sb + TILE_B + d1,     Alo + (size_t)(m0 + r1) * K + koff);
        }
        cp16(sb + 2 * TILE_B + d0,     Whi + (size_t)(n0 + r0) * K + koff);
        cp16(sb + 2 * TILE_B + d1,     Whi + (size_t)(n0 + r1) * K + koff);
        cp16(sb + 3 * TILE_B + d0,     Wlo + (size_t)(n0 + r0) * K + koff);
        cp16(sb + 3 * TILE_B + d1,     Wlo + (size_t)(n0 + r1) * K + koff);
        CP_COMMIT();
    };

    float4 rf[4];
    auto ldgA = [&](int c) {                 // gather only: fp32 rows
        const int koff = c * 32 + srcoff;
        const float* s0 = Af + (size_t)idS[r0] * K + koff;
        rf[0] = *(const float4*)s0; rf[1] = *(const float4*)(s0 + 4);
        const float* s1 = Af + (size_t)idS[r1] * K + koff;
        rf[2] = *(const float4*)s1; rf[3] = *(const float4*)(s1 + 4);
    };
    auto stsA = [&](int c) {                 // gather only: split + store hi/lo
        char* base = (char*)smdyn + (c % 3) * STAGE_B;
#pragma unroll
        for (int u = 0; u < 2; u++) {
            const float* f = (const float*)&rf[2 * u];
            const unsigned dd = (u == 0) ? d0 : d1;
            __nv_bfloat16 vh[8], vl[8];
#pragma unroll
            for (int j = 0; j < 8; j++) {
                __nv_bfloat16 h = __float2bfloat16(f[j]);
                vh[j] = h;
                vl[j] = __float2bfloat16(f[j] - __bfloat162float(h));
            }
            *(uint4*)(base + dd)          = *(uint4*)vh;
            *(uint4*)(base + TILE_B + dd) = *(uint4*)vl;
        }
    };

    // prologue: stages 0 and 1 in flight
    issue(0);
    issue(1);
    if constexpr (GATHER) ldgA(0);

    for (int c = 0; c < NC; c++) {
        if (c + 1 < NC) { CP_WAIT1(); } else { CP_WAIT0(); }
        if constexpr (GATHER) stsA(c);
        __syncthreads();
        if (c + 2 < NC) issue(c + 2);
        if constexpr (GATHER) { if (c + 1 < NC) ldgA(c + 1); }

        const unsigned sb  = smB + (unsigned)((c % 3) * STAGE_B);
        const unsigned aHi = sb;
        const unsigned aLo = sb + TILE_B;
        const unsigned wHi = sb + 2 * TILE_B;
        const unsigned wLo = sb + 3 * TILE_B;
#pragma unroll
        for (int ks = 0; ks < 2; ks++) {
            uint32_t bh[4][2], bl[4][2];
#pragma unroll
            for (int ntp = 0; ntp < 2; ntp++) {
                const int br = wn * 32 + ntp * 16 + b_nrow;
                const int bc = ks * 2 + b_c16;
                const unsigned wo = (unsigned)(br * 64 + ((bc ^ ((br >> 1) & 3)) << 4));
                ldsm_x4_b2(bh[2 * ntp], bh[2 * ntp + 1], wHi + wo);
                ldsm_x4_b2(bl[2 * ntp], bl[2 * ntp + 1], wLo + wo);
            }
#pragma unroll
            for (int mt = 0; mt < 4; mt++) {
                const int ar = wm * 64 + mt * 16 + a_mrow;
                const int ac = ks * 2 + a_c16;
                const unsigned ao = (unsigned)(ar * 64 + ((ac ^ ((ar >> 1) & 3)) << 4));
                uint32_t afh[4], afl[4];
                ldsm_x4(afh, aHi + ao);
                ldsm_x4(afl, aLo + ao);
#pragma unroll
                for (int nt = 0; nt < 4; nt++) mma16816(acc[mt][nt], afh, bh[nt]);
#pragma unroll
                for (int nt = 0; nt < 4; nt++) mma16816(acc[mt][nt], afl, bh[nt]);
#pragma unroll
                for (int nt = 0; nt < 4; nt++) mma16816(acc[mt][nt], afh, bl[nt]);
            }
        }
    }

    // epilogue
#pragma unroll
    for (int mt = 0; mt < 4; mt++)
#pragma unroll
        for (int nt = 0; nt < 4; nt++) {
            int row = m0 + wm * 64 + mt * 16 + (lane >> 2);
            int col = n0 + wn * 32 + nt * 8 + ((lane & 3) << 1);
            float2 bz = *(const float2*)(bias + col);
            float* c = acc[mt][nt];
            float y0 = c[0] + bz.x, y1 = c[1] + bz.y;
            float y2 = c[2] + bz.x, y3 = c[3] + bz.y;
            if (EP == 0) { y0 = siluf(y0); y1 = siluf(y1); y2 = siluf(y2); y3 = siluf(y3); }
            if (EP <= 1) {
                store_split2(Chi, Clo, (size_t)row * N + col, y0, y1);
                store_split2(Chi, Clo, (size_t)(row + 8) * N + col, y2, y3);
            } else {
                *(float2*)(Cf + (size_t)row * N + col)       = make_float2(y0, y1);
                *(float2*)(Cf + (size_t)(row + 8) * N + col) = make_float2(y2, y3);
            }
        }
}

// ---------------------------------------------------------------------------
// Pair-MLP kernel over UNIQUE pairs (unchanged from R10 — proven).
// ---------------------------------------------------------------------------
#define PAIRS_SMEM (2 * 128 * 264 * 2 + 2 * 2 * 128 * 40 * 2 + 256 * 4 + 512 * 4)

__global__ __launch_bounds__(256)
void pairs_mma_k(const __nv_bfloat16* __restrict__ Hhi, const __nv_bfloat16* __restrict__ Hlo,
                 const __nv_bfloat16* __restrict__ W1hi, const __nv_bfloat16* __restrict__ W1lo,
                 const float* __restrict__ b1, const float* __restrict__ w2,
                 float* __restrict__ O2)
{
    extern __shared__ __align__(16) char smraw[];
    __nv_bfloat16* Aphi = (__nv_bfloat16*)smraw;            // [128][264]
    __nv_bfloat16* Aplo = Aphi + 128 * 264;                 // [128][264]
    __nv_bfloat16* Wt   = Aplo + 128 * 264;                 // [2 buf][2 hl][128][40]
    int*   off1s = (int*)(Wt + 2 * 2 * 128 * 40);
    int*   off2s = off1s + 128;
    float* redS  = (float*)(off2s + 128);                   // [4][128]

    const int t = threadIdx.x, lane = t & 31, warp = t >> 5;
    const int wm = warp >> 2, wn = warp & 3;
    const int m0 = blockIdx.x * 128;

    if (t < 128) {
        int r = m0 + t, b = r / NPAIR_U, p = r - b * NPAIR_U;
        off1s[t] = (b * TEAMN + c_u1[p]) * 256;
        off2s[t] = (b * TEAMN + c_u2[p]) * 256;
    }
    __syncthreads();

    // ---- phase 1: build product tiles (hi/lo) ----
    {
        int cidx = t;
#pragma unroll 4
        for (int i = 0; i < 16; i++, cidx += 256) {
            int row = cidx >> 5;
            int ch  = (cidx & 31) << 3;
            int o1 = off1s[row] + ch, o2 = off2s[row] + ch;
            uint4 u1h = *(const uint4*)(Hhi + o1);
            uint4 u1l = *(const uint4*)(Hlo + o1);
            uint4 u2h = *(const uint4*)(Hhi + o2);
            uint4 u2l = *(const uint4*)(Hlo + o2);
            const __nv_bfloat162* p1h = (const __nv_bfloat162*)&u1h;
            const __nv_bfloat162* p1l = (const __nv_bfloat162*)&u1l;
            const __nv_bfloat162* p2h = (const __nv_bfloat162*)&u2h;
            const __nv_bfloat162* p2l = (const __nv_bfloat162*)&u2l;
            __nv_bfloat162 oph[4], opl[4];
#pragma unroll
            for (int j = 0; j < 4; j++) {
                float2 a   = __bfloat1622float2(p1h[j]);
                float2 al  = __bfloat1622float2(p1l[j]);
                float2 b_  = __bfloat1622float2(p2h[j]);
                float2 bl_ = __bfloat1622float2(p2l[j]);
                float f0 = (a.x + al.x) * (b_.x + bl_.x);
                float f1 = (a.y + al.y) * (b_.y + bl_.y);
                __nv_bfloat16 h0 = __float2bfloat16(f0), h1 = __float2bfloat16(f1);
                oph[j] = __halves2bfloat162(h0, h1);
                opl[j] = __halves2bfloat162(
                    __float2bfloat16(f0 - __bfloat162float(h0)),
                    __float2bfloat16(f1 - __bfloat162float(h1)));
            }
            *(uint4*)(Aphi + row * 264 + ch) = *(uint4*)oph;
            *(uint4*)(Aplo + row * 264 + ch) = *(uint4*)opl;
        }
    }

    float rowsum[4][2];
#pragma unroll
    for (int a = 0; a < 4; a++) { rowsum[a][0] = 0.f; rowsum[a][1] = 0.f; }

    const int a_mrow = ((lane >> 3) & 1) * 8 + (lane & 7);
    const int a_kc   = (lane >> 4) * 8;
    const int b_nrow = ((lane >> 4) & 1) * 8 + (lane & 7);
    const int b_kc   = ((lane >> 3) & 1) * 8;
    const unsigned aPhiB = smem_u32(Aphi);
    const unsigned aPloB = smem_u32(Aplo);
    const unsigned wB    = smem_u32(Wt);

    uint4 rwh[2], rwl[2];
#pragma unroll
    for (int u = 0; u < 2; u++) {    // prefetch n0=0, k0=0
        int idx = t + u * 256, row = idx >> 2, ch = (idx & 3) << 3;
        size_t go = (size_t)row * 256 + ch;
        rwh[u] = *(const uint4*)(W1hi + go);
        rwl[u] = *(const uint4*)(W1lo + go);
    }

    int buf = 0;
    for (int n0i = 0; n0i < 4; n0i++) {
        int n0 = n0i * 128;
        float acc[4][4][4];
#pragma unroll
        for (int a = 0; a < 4; a++)
#pragma unroll
            for (int b = 0; b < 4; b++)
#pragma unroll
                for (int c = 0; c < 4; c++) acc[a][b][c] = 0.f;

        for (int k0 = 0; k0 < 8; k0++) {
#pragma unroll
            for (int u = 0; u < 2; u++) {
                int idx = t + u * 256, row = idx >> 2, ch = (idx & 3) << 3;
                *(uint4*)(Wt + (buf * 2 + 0) * 5120 + row * 40 + ch) = rwh[u];
                *(uint4*)(Wt + (buf * 2 + 1) * 5120 + row * 40 + ch) = rwl[u];
            }
            __syncthreads();
            if (!(n0i == 3 && k0 == 7)) {
                int nk = k0 + 1, nn = n0i;
                if (nk == 8) { nk = 0; nn++; }
#pragma unroll
                for (int u = 0; u < 2; u++) {
                    int idx = t + u * 256, row = idx >> 2, ch = (idx & 3) << 3;
                    size_t go = (size_t)(nn * 128 + row) * 256 + nk * 32 + ch;
                    rwh[u] = *(const uint4*)(W1hi + go);
                    rwl[u] = *(const uint4*)(W1lo + go);
                }
            }
#pragma unroll
            for (int ks = 0; ks < 2; ks++) {
                int kpos = k0 * 32 + ks * 16;
                uint32_t bh[4][2], blo_[4][2];
#pragma unroll
                for (int ntp = 0; ntp < 2; ntp++) {
                    unsigned wo = (wn * 32 + ntp * 16 + b_nrow) * 40 + ks * 16 + b_kc;
                    ldsm_x4_b2(bh[2 * ntp],   bh[2 * ntp + 1],
                               wB + 2u * ((buf * 2 + 0) * 5120 + wo));
                    ldsm_x4_b2(blo_[2 * ntp], blo_[2 * ntp + 1],
                               wB + 2u * ((buf * 2 + 1) * 5120 + wo));
                }
#pragma unroll
                for (int mt = 0; mt < 4; mt++) {
                    unsigned ao = (wm * 64 + mt * 16 + a_mrow) * 264 + kpos + a_kc;
                    uint32_t af[4];
                    ldsm_x4(af, aPhiB + 2u * ao);
#pragma unroll
                    for (int nt = 0; nt < 4; nt++) mma16816(acc[mt][nt], af, bh[nt]);
#pragma unroll
                    for (int nt = 0; nt < 4; nt++) mma16816(acc[mt][nt], af, blo_[nt]);
                    ldsm_x4(af, aPloB + 2u * ao);
#pragma unroll
                    for (int nt = 0; nt < 4; nt++) mma16816(acc[mt][nt], af, bh[nt]);
                }
            }
            buf ^= 1;
        }
        // fold this n-chunk into rowsums
#pragma unroll
        for (int mt = 0; mt < 4; mt++)
#pragma unroll
            for (int nt = 0; nt < 4; nt++) {
                int col = n0 + wn * 32 + nt * 8 + ((lane & 3) << 1);
                float2 bz = *(const float2*)(b1 + col);
                float2 wz = *(const float2*)(w2 + col);
                float* c = acc[mt][nt];
                rowsum[mt][0] += siluf(c[0] + bz.x) * wz.x + siluf(c[1] + bz.y) * wz.y;
                rowsum[mt][1] += siluf(c[2] + bz.x) * wz.x + siluf(c[3] + bz.y) * wz.y;
            }
    }

    // reduce over the 4 lanes sharing a row, then across the 4 n-warps
#pragma unroll
    for (int mt = 0; mt < 4; mt++)
#pragma unroll
        for (int p = 0; p < 2; p++) {
            float v = rowsum[mt][p];
            v += __shfl_xor_sync(0xffffffffu, v, 1);
            v += __shfl_xor_sync(0xffffffffu, v, 2);
            rowsum[mt][p] = v;
        }
    __syncthreads();
    if ((lane & 3) == 0) {
#pragma unroll
        for (int mt = 0; mt < 4; mt++)
#pragma unroll
            for (int p = 0; p < 2; p++) {
                int r = wm * 64 + mt * 16 + (lane >> 2) + p * 8;
                redS[wn * 128 + r] = rowsum[mt][p];
            }
    }
    __syncthreads();
    if (t < 128) {
        float v = redS[t] + redS[128 + t] + redS[256 + t] + redS[384 + t];
        int r = m0 + t, b = r / NPAIR_U, p = r - b * NPAIR_U;
        O2[b * NPAIR + c_sA[p]] = v;   // (i,j)
        O2[b * NPAIR + c_sB[p]] = v;   // (j,i) — identical by symmetry
    }
}

// ---------------------------------------------------------------------------
// Final: score[p] = <wh[b,i1], h[b,i2]>, softmax per group-of-4, weighted sum.
// ---------------------------------------------------------------------------
__global__ __launch_bounds__(128)
void final_k(const __nv_bfloat16* __restrict__ Hhi, const __nv_bfloat16* __restrict__ Hlo,
             const float* __restrict__ WH, const float* __restrict__ O2,
             const float* __restrict__ mlp_b2, float* __restrict__ out)
{
    __shared__ float scoreS[4][NPAIR];
    const int wi = threadIdx.x >> 5, lane = threadIdx.x & 31;
    const int b = blockIdx.x * 4 + wi;
    const __nv_bfloat16* hbh = Hhi + (size_t)b * TEAMN * 256;
    const __nv_bfloat16* hbl = Hlo + (size_t)b * TEAMN * 256;
    const float* whb = WH + (size_t)b * TEAMN * 256;

    for (int p = 0; p < NPAIR; p++) {
        const float* wa = whb + c_i1[p] * 256;
        int ho = c_i2[p] * 256 + lane * 8;
        uint4 uh = *(const uint4*)(hbh + ho);
        uint4 ul = *(const uint4*)(hbl + ho);
        const __nv_bfloat162* ph = (const __nv_bfloat162*)&uh;
        const __nv_bfloat162* pl = (const __nv_bfloat162*)&ul;
        float xv[8];
        *(float4*)&xv[0] = *(const float4*)(wa + lane * 8);
        *(float4*)&xv[4] = *(const float4*)(wa + lane * 8 + 4);
        float s = 0.f;
#pragma unroll
        for (int j = 0; j < 4; j++) {
            float2 hh = __bfloat1622float2(ph[j]);
            float2 hl = __bfloat1622float2(pl[j]);
            s += xv[2 * j] * (hh.x + hl.x) + xv[2 * j + 1] * (hh.y + hl.y);
        }
#pragma unroll
        for (int off = 16; off > 0; off >>= 1)
            s += __shfl_down_sync(0xffffffffu, s, off);
        if (lane == 0) scoreS[wi][p] = s;
    }
    __syncwarp();

    float partial = 0.f;
    if (lane < TEAMN) {
        float sc[4];
#pragma unroll
        for (int j = 0; j < 4; j++) sc[j] = scoreS[wi][lane * 4 + j];
        float mx = fmaxf(fmaxf(sc[0], sc[1]), fmaxf(sc[2], sc[3]));
        float e[4], se = 0.f;
#pragma unroll
        for (int j = 0; j < 4; j++) { e[j] = __expf(sc[j] - mx); se += e[j]; }
        float bias2 = mlp_b2[0];
        float acc = 0.f;
#pragma unroll
        for (int j = 0; j < 4; j++)
            acc += e[j] * (O2[b * NPAIR + lane * 4 + j] + bias2);
        partial = acc / se;
    }
#pragma unroll
    for (int off = 16; off > 0; off >>= 1)
        partial += __shfl_down_sync(0xffffffffu, partial, off);
    if (lane == 0) out[b] = partial;
}

// ---------------------------------------------------------------------------
extern "C" void kernel_launch(void* const* d_in, const int* in_sizes, int n_in,
                              void* d_out, int out_size)
{
    const int*   team_ids = (const int*)  d_in[0];
    const float* emb      = (const float*)d_in[1];
    const float* fm_w1    = (const float*)d_in[2];
    const float* fm_b1    = (const float*)d_in[3];
    const float* fm_w2    = (const float*)d_in[4];
    const float* fm_b2    = (const float*)d_in[5];
    const float* att_w    = (const float*)d_in[6];
    const float* att_b    = (const float*)d_in[7];
    const float* mlp_w1   = (const float*)d_in[8];
    const float* mlp_b1   = (const float*)d_in[9];
    const float* mlp_w2   = (const float*)d_in[10];
    const float* mlp_b2   = (const float*)d_in[11];
    float* out = (float*)d_out;

    void *p_h1hi, *p_h1lo, *p_hhi, *p_hlo, *p_wh, *p_o2;
    void *p_w1hi, *p_w1lo, *p_w2hi, *p_w2lo, *p_awhi, *p_awlo, *p_m1hi, *p_m1lo;
    cudaGetSymbolAddress(&p_h1hi, g_h1hi); cudaGetSymbolAddress(&p_h1lo, g_h1lo);
    cudaGetSymbolAddress(&p_hhi,  g_hhi);  cudaGetSymbolAddress(&p_hlo,  g_hlo);
    cudaGetSymbolAddress(&p_wh,   g_wh);   cudaGetSymbolAddress(&p_o2,   g_o2);
    cudaGetSymbolAddress(&p_w1hi, g_w1hi); cudaGetSymbolAddress(&p_w1lo, g_w1lo);
    cudaGetSymbolAddress(&p_w2hi, g_w2hi); cudaGetSymbolAddress(&p_w2lo, g_w2lo);
    cudaGetSymbolAddress(&p_awhi, g_awhi); cudaGetSymbolAddress(&p_awlo, g_awlo);
    cudaGetSymbolAddress(&p_m1hi, g_m1hi); cudaGetSymbolAddress(&p_m1lo, g_m1lo);

    cudaFuncSetAttribute(mma_gemm_k<256, 0, true>,
                         cudaFuncAttributeMaxDynamicSharedMemorySize, GEMM_SMEM);
    cudaFuncSetAttribute(mma_gemm_k<512, 1, false>,
                         cudaFuncAttributeMaxDynamicSharedMemorySize, GEMM_SMEM);
    cudaFuncSetAttribute(mma_gemm_k<256, 2, false>,
                         cudaFuncAttributeMaxDynamicSharedMemorySize, GEMM_SMEM);
    cudaFuncSetAttribute(pairs_mma_k,
                         cudaFuncAttributeMaxDynamicSharedMemorySize, PAIRS_SMEM);

    // split ALL weights in one launch (emb is split in-register inside fm1)
    splitw_k<<<(WTOT + 255) / 256, 256>>>(
        fm_w1, fm_w2, att_w, mlp_w1,
        (__nv_bfloat16*)p_w1hi, (__nv_bfloat16*)p_w1lo,
        (__nv_bfloat16*)p_w2hi, (__nv_bfloat16*)p_w2lo,
        (__nv_bfloat16*)p_awhi, (__nv_bfloat16*)p_awlo,
        (__nv_bfloat16*)p_m1hi, (__nv_bfloat16*)p_m1lo);

    // fm1: gather fp32 emb + in-register split + silu(x @ fm_w1^T + b1) -> h1 (hi/lo)
    mma_gemm_k<256, 0, true><<<dim3(4, NROW / 128), 256, GEMM_SMEM>>>(
        emb, nullptr, nullptr,
        (const __nv_bfloat16*)p_w1hi, (const __nv_bfloat16*)p_w1lo,
        fm_b1, (__nv_bfloat16*)p_h1hi, (__nv_bfloat16*)p_h1lo, nullptr, team_ids, 512);
    // fm2: h1 @ fm_w2^T + b2 -> h (hi/lo)
    mma_gemm_k<512, 1, false><<<dim3(2, NROW / 128), 256, GEMM_SMEM>>>(
        nullptr, (const __nv_bfloat16*)p_h1hi, (const __nv_bfloat16*)p_h1lo,
        (const __nv_bfloat16*)p_w2hi, (const __nv_bfloat16*)p_w2lo,
        fm_b2, (__nv_bfloat16*)p_hhi, (__nv_bfloat16*)p_hlo, nullptr, nullptr, 256);
    // att (hoisted per member): h @ att_w^T + att_b -> wh (fp32)
    mma_gemm_k<256, 2, false><<<dim3(2, NROW / 128), 256, GEMM_SMEM>>>(
        nullptr, (const __nv_bfloat16*)p_hhi, (const __nv_bfloat16*)p_hlo,
        (const __nv_bfloat16*)p_awhi, (const __nv_bfloat16*)p_awlo,
        att_b, nullptr, nullptr, (float*)p_wh, nullptr, 256);
    // pair MLP over unique pairs + order2 scatter -> o2
    pairs_mma_k<<<MROW_U / 128, 256, PAIRS_SMEM>>>(
        (const __nv_bfloat16*)p_hhi, (const __nv_bfloat16*)p_hlo,
        (const __nv_bfloat16*)p_m1hi, (const __nv_bfloat16*)p_m1lo,
        mlp_b1, mlp_w2, (float*)p_o2);
    // scores + softmax + weighted sum
    final_k<<<BSZ / 4, 128>>>(
        (const __nv_bfloat16*)p_hhi, (const __nv_bfloat16*)p_hlo,
        (const float*)p_wh, (const float*)p_o2, mlp_b2, out);
}